// round 11
// baseline (speedup 1.0000x reference)
#include <cuda_runtime.h>
#include <cuda_fp16.h>
#include <math.h>
#include <stdint.h>

#define S_DIM 4096
#define E_DIM 2048
#define H_NUM 16
#define D_HEAD 128
#define T_NUM 32

// ---------------------------------------------------------------------------
// Scratch (__device__ globals; allocation-free rule) — single fp16 pipeline
// ---------------------------------------------------------------------------
__device__ __half g_x16[S_DIM * E_DIM];
__device__ __half g_wqT[E_DIM * E_DIM];
__device__ __half g_wkT[E_DIM * E_DIM];
__device__ __half g_wvT[E_DIM * E_DIM];
__device__ __half g_woT[E_DIM * E_DIM];
__device__ __half g_q16[H_NUM * S_DIM * D_HEAD];
__device__ __half g_k16[H_NUM * S_DIM * D_HEAD];
__device__ __half g_v16[H_NUM * S_DIM * D_HEAD];
__device__ __half g_att[S_DIM * E_DIM];

// ---------------------------------------------------------------------------
// base-ISA PTX helpers (compute_103 virtual arch: no tcgen05/TMA)
// ---------------------------------------------------------------------------
__device__ __forceinline__ uint32_t smem_u32(const void* p) {
    uint32_t a;
    asm("{ .reg .u64 t; cvta.to.shared.u64 t, %1; cvt.u32.u64 %0, t; }" : "=r"(a) : "l"(p));
    return a;
}

#define CP_ASYNC16(dst, src) \
    asm volatile("cp.async.cg.shared.global [%0], [%1], 16;" :: "r"(dst), "l"(src))
#define CP_COMMIT() asm volatile("cp.async.commit_group;" ::: "memory")
#define CP_WAIT2() asm volatile("cp.async.wait_group 2;" ::: "memory")
#define CP_WAIT1() asm volatile("cp.async.wait_group 1;" ::: "memory")
#define CP_WAIT0() asm volatile("cp.async.wait_group 0;" ::: "memory")

#define LDSM4(r0, r1, r2, r3, addr) \
    asm volatile("ldmatrix.sync.aligned.m8n8.x4.shared.b16 {%0,%1,%2,%3}, [%4];" \
        : "=r"(r0), "=r"(r1), "=r"(r2), "=r"(r3) : "r"(addr))
#define LDSM4T(r0, r1, r2, r3, addr) \
    asm volatile("ldmatrix.sync.aligned.m8n8.x4.trans.shared.b16 {%0,%1,%2,%3}, [%4];" \
        : "=r"(r0), "=r"(r1), "=r"(r2), "=r"(r3) : "r"(addr))

#define MMA16816(d, a, b) \
    asm volatile("mma.sync.aligned.m16n8k16.row.col.f32.f16.f16.f32 " \
        "{%0,%1,%2,%3}, {%4,%5,%6,%7}, {%8,%9}, {%0,%1,%2,%3};" \
        : "+f"((d)[0]), "+f"((d)[1]), "+f"((d)[2]), "+f"((d)[3]) \
        : "r"((a)[0]), "r"((a)[1]), "r"((a)[2]), "r"((a)[3]), \
          "r"((b)[0]), "r"((b)[1]))

__device__ __forceinline__ uint32_t pack_h2(float a, float b) {
    __half2 v = __floats2half2_rn(a, b);
    return *(uint32_t*)&v;
}

// ---------------------------------------------------------------------------
// fp32 -> fp16 convert (x)
// ---------------------------------------------------------------------------
__global__ void convert_kernel(const float* __restrict__ in,
                               __half* __restrict__ out, int n)
{
    int i = (blockIdx.x * blockDim.x + threadIdx.x) * 4;
    if (i >= n) return;
    float4 v = *(const float4*)(in + i);
    *(__half2*)(out + i)     = __floats2half2_rn(v.x, v.y);
    *(__half2*)(out + i + 2) = __floats2half2_rn(v.z, v.w);
}

// ---------------------------------------------------------------------------
// fused transpose of all 4 weight matrices: w[K,N] -> wT[N,K] single fp16
// ---------------------------------------------------------------------------
__global__ void transpose4(const float* __restrict__ wq, const float* __restrict__ wk,
                           const float* __restrict__ wv, const float* __restrict__ wo)
{
    __shared__ float tile[32][33];
    const float* w;
    __half* oT;
    switch (blockIdx.z) {
        case 0:  w = wq; oT = g_wqT; break;
        case 1:  w = wk; oT = g_wkT; break;
        case 2:  w = wv; oT = g_wvT; break;
        default: w = wo; oT = g_woT; break;
    }
    int n = blockIdx.x * 32 + threadIdx.x;
    int k0 = blockIdx.y * 32;
#pragma unroll
    for (int j = 0; j < 32; j += 8)
        tile[threadIdx.y + j][threadIdx.x] = w[(k0 + threadIdx.y + j) * E_DIM + n];
    __syncthreads();
#pragma unroll
    for (int j = 0; j < 32; j += 8) {
        int orow = blockIdx.x * 32 + threadIdx.y + j;
        int ocol = k0 + threadIdx.x;
        oT[orow * E_DIM + ocol] = __float2half(tile[threadIdx.x][threadIdx.y + j]);
    }
}

// ---------------------------------------------------------------------------
// HMMA fp16 GEMM — single-term. CTA 256x128, 512 threads (16 warps 4Mx4N),
// K-chunk 64, cp.async double buffer. (At the mma.sync issue-rate wall.)
// mode 0: fp32 row-major out[M,2048] (A = g_att, B = woT)
// mode 3: fused QKV — blockIdx.x = which*16 + nb; RoPE for Q,K; fp16 outs
// ---------------------------------------------------------------------------
#define ROW_B 144
#define A_TILE_B (256 * ROW_B)       // 36864
#define B_TILE_B (128 * ROW_B)       // 18432
#define STAGE_B (A_TILE_B + B_TILE_B)  // 55296
#define EPI_B (256 * 132 * 4)        // 135168 fp32 epilogue tile
#define GEMM_SMEM (EPI_B > 2 * STAGE_B ? EPI_B : 2 * STAGE_B)   // 135168

__global__ __launch_bounds__(512, 1)
void gemm_mma(const __half* __restrict__ As, const __half* __restrict__ Bs,
              float* __restrict__ outf, const float* __restrict__ rope, int mode)
{
    extern __shared__ char smem[];
    const uint32_t smem_base = smem_u32(smem);
    const int tid = threadIdx.x;
    const int wid = tid >> 5;
    const int lane = tid & 31;
    const int m0 = blockIdx.y * 256;
    const int wM = wid >> 2;         // 0..3
    const int wN = wid & 3;          // 0..3

    const __half* b_p;
    int n0, hsel, which = -1;
    if (mode == 3) {
        which = blockIdx.x >> 4;
        int nb = blockIdx.x & 15;
        n0 = nb * 128; hsel = nb;
        b_p = (which == 0) ? g_wqT : (which == 1) ? g_wkT : g_wvT;
    } else {
        n0 = blockIdx.x * 128; hsel = blockIdx.x;
        b_p = Bs;
    }

    const char* srcA = (const char*)(As + (size_t)m0 * E_DIM);
    const char* srcB = (const char*)(b_p + (size_t)n0 * E_DIM);

    auto issue_chunk = [&](int c, int p) {
        uint32_t sb = smem_base + p * STAGE_B;
        const int kb = c * 128;
#pragma unroll
        for (int i = 0; i < 4; i++) {
            int idx = tid + i * 512;
            int row = idx >> 3, c16 = idx & 7;
            uint32_t d = row * ROW_B + c16 * 16;
            CP_ASYNC16(sb + d, srcA + (size_t)row * 4096 + kb + c16 * 16);
        }
#pragma unroll
        for (int i = 0; i < 2; i++) {
            int idx = tid + i * 512;
            int row = idx >> 3, c16 = idx & 7;
            uint32_t d = row * ROW_B + c16 * 16;
            CP_ASYNC16(sb + A_TILE_B + d, srcB + (size_t)row * 4096 + kb + c16 * 16);
        }
    };

    float acc[4][4][4];
#pragma unroll
    for (int mt = 0; mt < 4; mt++)
#pragma unroll
        for (int nt = 0; nt < 4; nt++)
#pragma unroll
            for (int e = 0; e < 4; e++) acc[mt][nt][e] = 0.0f;

    const int a_row = (lane & 15);
    const int a_kb = (lane >> 4) * 16;
    const int b_nrow = (lane & 7) | ((lane & 16) >> 1);
    const int b_kb = (lane & 8) ? 16 : 0;

    issue_chunk(0, 0);
    CP_COMMIT();

    for (int c = 0; c < 32; c++) {
        if (c + 1 < 32) {
            issue_chunk(c + 1, (c + 1) & 1);
            CP_COMMIT();
            CP_WAIT1();
        } else {
            CP_WAIT0();
        }
        __syncthreads();

        uint32_t sb = smem_base + (c & 1) * STAGE_B;
        uint32_t aA = sb + (wM * 64 + a_row) * ROW_B + a_kb;
        uint32_t bB = sb + A_TILE_B + (wN * 32 + b_nrow) * ROW_B + b_kb;

#pragma unroll
        for (int ks = 0; ks < 4; ks++) {
            uint32_t a[4][4], b[4][2];
#pragma unroll
            for (int mt = 0; mt < 4; mt++) {
                LDSM4(a[mt][0], a[mt][1], a[mt][2], a[mt][3],
                      aA + mt * (16 * ROW_B) + ks * 32);
            }
#pragma unroll
            for (int bt = 0; bt < 2; bt++) {
                LDSM4(b[bt * 2][0], b[bt * 2][1], b[bt * 2 + 1][0], b[bt * 2 + 1][1],
                      bB + bt * (16 * ROW_B) + ks * 32);
            }
#pragma unroll
            for (int mt = 0; mt < 4; mt++)
#pragma unroll
                for (int nt = 0; nt < 4; nt++)
                    MMA16816(acc[mt][nt], a[mt], b[nt]);
        }
        __syncthreads();
    }

    // epilogue through smem so RoPE pairs d/d+64 are thread-local
    float* csm = (float*)smem;     // [256][132]
    const int g = lane >> 2;
    const int tg = lane & 3;
#pragma unroll
    for (int mt = 0; mt < 4; mt++)
#pragma unroll
        for (int nt = 0; nt < 4; nt++) {
            int r = wM * 64 + mt * 16 + g;
            int col = wN * 32 + nt * 8 + tg * 2;
            csm[r * 132 + col]           = acc[mt][nt][0];
            csm[r * 132 + col + 1]       = acc[mt][nt][1];
            csm[(r + 8) * 132 + col]     = acc[mt][nt][2];
            csm[(r + 8) * 132 + col + 1] = acc[mt][nt][3];
        }
    __syncthreads();

#pragma unroll 4
    for (int it = 0; it < 32; it++) {
        int idx = tid + it * 512;
        int row = idx >> 6;
        int d = idx & 63;
        float lo = csm[row * 132 + d];
        float hi = csm[row * 132 + d + 64];
        int s = m0 + row;
        if (mode == 0) {
            float* orow = outf + (size_t)s * E_DIM + n0;
            orow[d] = lo;
            orow[d + 64] = hi;
        } else {
            if (which <= 1) {              // RoPE for Q and K
                float ang = rope[s * (D_HEAD / 2) + d];
                float sn, cs;
                __sincosf(ang, &sn, &cs);
                float nlo = lo * cs - hi * sn;
                float nhi = hi * cs + lo * sn;
                lo = nlo; hi = nhi;
            }
            size_t base = ((size_t)hsel * S_DIM + s) * D_HEAD;
            __half* dst = (which == 0) ? g_q16 : (which == 1) ? g_k16 : g_v16;
            dst[base + d]      = __float2half(lo);
            dst[base + d + 64] = __float2half(hi);
        }
    }
}

// ---------------------------------------------------------------------------
// Block-sparse attention, single-term fp16 mma.sync, CTA per (q-tile, head).
// R11: double-buffered K and V (prefetch issued right after K-ready barrier),
// only 2 __syncthreads per tile; diag softmax work limited to live fragments.
// smem: Q, K0, K1, V0, V1  (5 x 32KB, 256B swizzled rows) = 160KB
// ---------------------------------------------------------------------------
#define NEG_BIG (-1e10f)
#define ATT_TILE 32768
#define ATT_SMEM (5 * ATT_TILE)   // 163840

__global__ __launch_bounds__(256, 1)
void attn_mma(const int* __restrict__ anchors, int kanch)
{
    extern __shared__ char smn[];
    __shared__ int s_tiles[16];
    __shared__ int s_cnt;
    const uint32_t base = smem_u32(smn);
    const uint32_t Qb = base;
    const uint32_t Kb = base + ATT_TILE;       // two K buffers
    const uint32_t Vb = base + 3 * ATT_TILE;   // two V buffers

    const int t = blockIdx.x, h = blockIdx.y;
    const int tid = threadIdx.x;
    const int w = tid >> 5, lane = tid & 31;
    const int g = lane >> 2, tq = lane & 3;
    const float scale = 0.088388347648318447f;

    // build filtered tile list: anchors <= t (duplicates kept), then local t
    const int abase = (h * T_NUM + t) * kanch;
    if (tid == 0) {
        int n = 0;
        for (int i = 0; i < kanch; i++) {
            int a = anchors[abase + i];
            if (a <= t) s_tiles[n++] = a;
        }
        s_tiles[n++] = t;
        s_cnt = n;
    }
    __syncthreads();
    const int cnt = s_cnt;
    int tile = s_tiles[0];

    auto load_tile = [&](uint32_t dst, const __half* src, int tl) {
        const char* p = (const char*)(src + ((size_t)h * S_DIM + (size_t)tl * 128) * D_HEAD);
        for (int i = tid; i < 2048; i += 256) {
            int row = i >> 4, c16 = i & 15;
            uint32_t off = row * 256 + ((c16 ^ (row & 7)) << 4);
            CP_ASYNC16(dst + off, p + (size_t)row * 256 + c16 * 16);
        }
    };

    // prologue: group0 = Q + K0 ; group1 = V0
    load_tile(Qb, g_q16, t);
    load_tile(Kb, g_k16, tile);
    CP_COMMIT();
    load_tile(Vb, g_v16, tile);
    CP_COMMIT();

    float o[16][4];
#pragma unroll
    for (int j = 0; j < 16; j++)
#pragma unroll
        for (int e = 0; e < 4; e++) o[j][e] = 0.0f;
    float m0 = -1e30f, m1 = -1e30f, l0 = 0.0f, l1 = 0.0f;

    const int wrow = w * 16;
    const int arow = wrow + (lane & 15);
    const int asw = arow & 7;
    const int ahc = lane >> 4;
    const int bnr = (lane & 7) | ((lane & 16) >> 1);
    const int bhc = (lane & 8) >> 3;
    const int vrl = lane & 15;
    const int vhc = lane >> 4;

    for (int it = 0; it < cnt; it++) {
        const bool have_next = (it + 1 < cnt);
        const int nx = have_next ? s_tiles[it + 1] : 0;
        const bool isdiag = (tile == t);
        const uint32_t Kcur = Kb + (uint32_t)(it & 1) * ATT_TILE;
        const uint32_t Vcur = Vb + (uint32_t)(it & 1) * ATT_TILE;

        // K_it ready (commit order: ...K_i, V_i -> 1 group after K_i)
        CP_WAIT1();
        __syncthreads();

        // prefetch next K and V into the other buffers (WAR-safe: other buffer
        // was last read in tile it-1, and every warp passed the barrier above)
        if (have_next) {
            load_tile(Kb + (uint32_t)((it + 1) & 1) * ATT_TILE, g_k16, nx);
            CP_COMMIT();
            load_tile(Vb + (uint32_t)((it + 1) & 1) * ATT_TILE, g_v16, nx);
            CP_COMMIT();
        }

        // ---- S = Q K^T (single term); skip fully-masked K blocks on diag ----
        float s[16][4];
#pragma unroll
        for (int j = 0; j < 16; j++)
#pragma unroll
            for (int e = 0; e < 4; e++) s[j][e] = 0.0f;

#pragma unroll
        for (int ks = 0; ks < 8; ks++) {
            uint32_t q4[4];
            uint32_t aoff = arow * 256 + (((ks * 2 + ahc) ^ asw) << 4);
            LDSM4(q4[0], q4[1], q4[2], q4[3], Qb + aoff);
#pragma unroll
            for (int nb = 0; nb < 8; nb++) {
                if (isdiag && nb > w) continue;
                int br = nb * 16 + bnr;
                uint32_t boff = br * 256 + (((ks * 2 + bhc) ^ (br & 7)) << 4);
                uint32_t k4[4];
                LDSM4(k4[0], k4[1], k4[2], k4[3], Kcur + boff);
                uint32_t b0[2] = {k4[0], k4[1]}, b1[2] = {k4[2], k4[3]};
                MMA16816(s[2 * nb],     q4, b0);
                MMA16816(s[2 * nb + 1], q4, b1);
            }
        }

        // ---- mask + online softmax (only live fragments on diag) ----
        const int jmax = isdiag ? (2 * w + 2) : 16;
        const int qp0 = t * 128 + wrow + g;
        const int qp1 = qp0 + 8;
        const int kb = tile * 128 + 2 * tq;
        float mx0 = -1e30f, mx1 = -1e30f;
#pragma unroll
        for (int j = 0; j < 16; j++) {
            if (j >= jmax) continue;
            int kc = kb + 8 * j;
            s[j][0] = (kc     > qp0) ? NEG_BIG : s[j][0] * scale;
            s[j][1] = (kc + 1 > qp0) ? NEG_BIG : s[j][1] * scale;
            s[j][2] = (kc     > qp1) ? NEG_BIG : s[j][2] * scale;
            s[j][3] = (kc + 1 > qp1) ? NEG_BIG : s[j][3] * scale;
            mx0 = fmaxf(mx0, fmaxf(s[j][0], s[j][1]));
            mx1 = fmaxf(mx1, fmaxf(s[j][2], s[j][3]));
        }
        mx0 = fmaxf(mx0, __shfl_xor_sync(0xffffffffu, mx0, 1));
        mx0 = fmaxf(mx0, __shfl_xor_sync(0xffffffffu, mx0, 2));
        mx1 = fmaxf(mx1, __shfl_xor_sync(0xffffffffu, mx1, 1));
        mx1 = fmaxf(mx1, __shfl_xor_sync(0xffffffffu, mx1, 2));
        const float mn0 = fmaxf(m0, mx0), mn1 = fmaxf(m1, mx1);
        const float f0 = __expf(m0 - mn0), f1 = __expf(m1 - mn1);
        float ls0 = 0.0f, ls1 = 0.0f;
#pragma unroll
        for (int j = 0; j < 16; j++) {
            if (j >= jmax) continue;
            s[j][0] = __expf(s[j][0] - mn0);
            s[j][1] = __expf(s[j][1] - mn0);
            s[j][2] = __expf(s[j][2] - mn1);
            s[j][3] = __expf(s[j][3] - mn1);
            ls0 += s[j][0] + s[j][1];
            ls1 += s[j][2] + s[j][3];
        }
        ls0 += __shfl_xor_sync(0xffffffffu, ls0, 1);
        ls0 += __shfl_xor_sync(0xffffffffu, ls0, 2);
        ls1 += __shfl_xor_sync(0xffffffffu, ls1, 1);
        ls1 += __shfl_xor_sync(0xffffffffu, ls1, 2);
        l0 = l0 * f0 + ls0; l1 = l1 * f1 + ls1;
        m0 = mn0; m1 = mn1;
#pragma unroll
        for (int j = 0; j < 16; j++) {
            o[j][0] *= f0; o[j][1] *= f0;
            o[j][2] *= f1; o[j][3] *= f1;
        }

        // V_it ready (2 groups committed after V_i if prefetch issued, else 0)
        if (have_next) CP_WAIT2(); else CP_WAIT0();
        __syncthreads();

        // ---- O += P V (single term); skip all-zero P chunks on diag ----
#pragma unroll
        for (int ks = 0; ks < 8; ks++) {
            if (isdiag && ks > w) continue;
            uint32_t ph[4];
            ph[0] = pack_h2(s[2 * ks][0], s[2 * ks][1]);
            ph[1] = pack_h2(s[2 * ks][2], s[2 * ks][3]);
            ph[2] = pack_h2(s[2 * ks + 1][0], s[2 * ks + 1][1]);
            ph[3] = pack_h2(s[2 * ks + 1][2], s[2 * ks + 1][3]);
            int vr = ks * 16 + vrl;
#pragma unroll
            for (int dd = 0; dd < 8; dd++) {
                uint32_t voff = vr * 256 + (((dd * 2 + vhc) ^ (vr & 7)) << 4);
                uint32_t v4[4];
                LDSM4T(v4[0], v4[1], v4[2], v4[3], Vcur + voff);
                uint32_t b0[2] = {v4[0], v4[1]}, b1[2] = {v4[2], v4[3]};
                MMA16816(o[2 * dd],     ph, b0);
                MMA16816(o[2 * dd + 1], ph, b1);
            }
        }

        tile = nx;
    }

    // ---- epilogue: normalize, fp16 att to [S, H*D] ----
    const float i0 = 1.0f / l0, i1 = 1.0f / l1;
    const int s0 = t * 128 + wrow + g, s1 = s0 + 8;
#pragma unroll
    for (int j = 0; j < 16; j++) {
        int col = h * D_HEAD + 8 * j + 2 * tq;
        *(uint32_t*)(g_att + (size_t)s0 * E_DIM + col) = pack_h2(o[j][0] * i0, o[j][1] * i0);
        *(uint32_t*)(g_att + (size_t)s1 * E_DIM + col) = pack_h2(o[j][2] * i1, o[j][3] * i1);
    }
}

// ---------------------------------------------------------------------------
extern "C" void kernel_launch(void* const* d_in, const int* in_sizes, int n_in,
                              void* d_out, int out_size)
{
    const float* x    = (const float*)d_in[0];
    const float* wq   = (const float*)d_in[1];
    const float* wk   = (const float*)d_in[2];
    const float* wv   = (const float*)d_in[3];
    const float* wo   = (const float*)d_in[4];
    const float* rope = (const float*)d_in[5];
    const int* anchors = (const int*)d_in[6];
    float* out = (float*)d_out;

    const int kanch = in_sizes[6] / (H_NUM * T_NUM);  // 8

    __half *x16, *woT, *att;
    cudaGetSymbolAddress((void**)&x16, g_x16);
    cudaGetSymbolAddress((void**)&woT, g_woT);
    cudaGetSymbolAddress((void**)&att, g_att);

    cudaFuncSetAttribute(gemm_mma, cudaFuncAttributeMaxDynamicSharedMemorySize, GEMM_SMEM);
    cudaFuncSetAttribute(attn_mma, cudaFuncAttributeMaxDynamicSharedMemorySize, ATT_SMEM);

    // 1. convert x -> fp16
    convert_kernel<<<(S_DIM * E_DIM / 4 + 255) / 256, 256>>>(x, x16, S_DIM * E_DIM);

    // 2. fused transpose of all weights (single fp16)
    dim3 tgrid(E_DIM / 32, E_DIM / 32, 4), tblk(32, 8);
    transpose4<<<tgrid, tblk>>>(wq, wk, wv, wo);

    // 3. fused QKV projection (RoPE inside), head-major fp16
    dim3 qkvgrid(48, S_DIM / 256);  // (48, 16)
    gemm_mma<<<qkvgrid, 512, GEMM_SMEM>>>(x16, nullptr, nullptr, rope, 3);

    // 4. block-sparse attention (double-buffered K/V, causal skips)
    dim3 agrid(T_NUM, H_NUM);
    attn_mma<<<agrid, 256, ATT_SMEM>>>(anchors, kanch);

    // 5. out projection -> d_out
    dim3 ogrid(E_DIM / 128, S_DIM / 256);  // (16, 16)
    gemm_mma<<<ogrid, 512, GEMM_SMEM>>>(att, woT, out, nullptr, 0);
}

// round 12
// speedup vs baseline: 1.0077x; 1.0077x over previous
#include <cuda_runtime.h>
#include <cuda_fp16.h>
#include <math.h>
#include <stdint.h>

#define S_DIM 4096
#define E_DIM 2048
#define H_NUM 16
#define D_HEAD 128
#define T_NUM 32

// ---------------------------------------------------------------------------
// Scratch (__device__ globals; allocation-free rule) — single fp16 pipeline
// ---------------------------------------------------------------------------
__device__ __half g_x16[S_DIM * E_DIM];
__device__ __half g_wqT[E_DIM * E_DIM];
__device__ __half g_wkT[E_DIM * E_DIM];
__device__ __half g_wvT[E_DIM * E_DIM];
__device__ __half g_woT[E_DIM * E_DIM];
__device__ __half g_q16[H_NUM * S_DIM * D_HEAD];
__device__ __half g_k16[H_NUM * S_DIM * D_HEAD];
__device__ __half g_v16[H_NUM * S_DIM * D_HEAD];
__device__ __half g_att[S_DIM * E_DIM];

// ---------------------------------------------------------------------------
// base-ISA PTX helpers (compute_103 virtual arch: no tcgen05/TMA)
// ---------------------------------------------------------------------------
__device__ __forceinline__ uint32_t smem_u32(const void* p) {
    uint32_t a;
    asm("{ .reg .u64 t; cvta.to.shared.u64 t, %1; cvt.u32.u64 %0, t; }" : "=r"(a) : "l"(p));
    return a;
}

#define CP_ASYNC16(dst, src) \
    asm volatile("cp.async.cg.shared.global [%0], [%1], 16;" :: "r"(dst), "l"(src))
#define CP_COMMIT() asm volatile("cp.async.commit_group;" ::: "memory")
#define CP_WAIT1() asm volatile("cp.async.wait_group 1;" ::: "memory")
#define CP_WAIT0() asm volatile("cp.async.wait_group 0;" ::: "memory")

#define LDSM4(r0, r1, r2, r3, addr) \
    asm volatile("ldmatrix.sync.aligned.m8n8.x4.shared.b16 {%0,%1,%2,%3}, [%4];" \
        : "=r"(r0), "=r"(r1), "=r"(r2), "=r"(r3) : "r"(addr))
#define LDSM4T(r0, r1, r2, r3, addr) \
    asm volatile("ldmatrix.sync.aligned.m8n8.x4.trans.shared.b16 {%0,%1,%2,%3}, [%4];" \
        : "=r"(r0), "=r"(r1), "=r"(r2), "=r"(r3) : "r"(addr))

#define MMA16816(d, a, b) \
    asm volatile("mma.sync.aligned.m16n8k16.row.col.f32.f16.f16.f32 " \
        "{%0,%1,%2,%3}, {%4,%5,%6,%7}, {%8,%9}, {%0,%1,%2,%3};" \
        : "+f"((d)[0]), "+f"((d)[1]), "+f"((d)[2]), "+f"((d)[3]) \
        : "r"((a)[0]), "r"((a)[1]), "r"((a)[2]), "r"((a)[3]), \
          "r"((b)[0]), "r"((b)[1]))

__device__ __forceinline__ uint32_t pack_h2(float a, float b) {
    __half2 v = __floats2half2_rn(a, b);
    return *(uint32_t*)&v;
}

// ---------------------------------------------------------------------------
// fp32 -> fp16 convert (x)
// ---------------------------------------------------------------------------
__global__ void convert_kernel(const float* __restrict__ in,
                               __half* __restrict__ out, int n)
{
    int i = (blockIdx.x * blockDim.x + threadIdx.x) * 4;
    if (i >= n) return;
    float4 v = *(const float4*)(in + i);
    *(__half2*)(out + i)     = __floats2half2_rn(v.x, v.y);
    *(__half2*)(out + i + 2) = __floats2half2_rn(v.z, v.w);
}

// ---------------------------------------------------------------------------
// fused transpose of all 4 weight matrices: w[K,N] -> wT[N,K] single fp16
// ---------------------------------------------------------------------------
__global__ void transpose4(const float* __restrict__ wq, const float* __restrict__ wk,
                           const float* __restrict__ wv, const float* __restrict__ wo)
{
    __shared__ float tile[32][33];
    const float* w;
    __half* oT;
    switch (blockIdx.z) {
        case 0:  w = wq; oT = g_wqT; break;
        case 1:  w = wk; oT = g_wkT; break;
        case 2:  w = wv; oT = g_wvT; break;
        default: w = wo; oT = g_woT; break;
    }
    int n = blockIdx.x * 32 + threadIdx.x;
    int k0 = blockIdx.y * 32;
#pragma unroll
    for (int j = 0; j < 32; j += 8)
        tile[threadIdx.y + j][threadIdx.x] = w[(k0 + threadIdx.y + j) * E_DIM + n];
    __syncthreads();
#pragma unroll
    for (int j = 0; j < 32; j += 8) {
        int orow = blockIdx.x * 32 + threadIdx.y + j;
        int ocol = k0 + threadIdx.x;
        oT[orow * E_DIM + ocol] = __float2half(tile[threadIdx.x][threadIdx.y + j]);
    }
}

// ---------------------------------------------------------------------------
// HMMA fp16 GEMM — single-term. CTA 256x128, 512 threads (16 warps 4Mx4N),
// K-chunk 64, cp.async double buffer. (At the mma.sync issue-rate wall.)
// mode 0: fp32 row-major out[M,2048] (A = g_att, B = woT)
// mode 3: fused QKV — blockIdx.x = which*16 + nb; RoPE for Q,K; fp16 outs
// ---------------------------------------------------------------------------
#define ROW_B 144
#define A_TILE_B (256 * ROW_B)       // 36864
#define B_TILE_B (128 * ROW_B)       // 18432
#define STAGE_B (A_TILE_B + B_TILE_B)  // 55296
#define EPI_B (256 * 132 * 4)        // 135168 fp32 epilogue tile
#define GEMM_SMEM (EPI_B > 2 * STAGE_B ? EPI_B : 2 * STAGE_B)   // 135168

__global__ __launch_bounds__(512, 1)
void gemm_mma(const __half* __restrict__ As, const __half* __restrict__ Bs,
              float* __restrict__ outf, const float* __restrict__ rope, int mode)
{
    extern __shared__ char smem[];
    const uint32_t smem_base = smem_u32(smem);
    const int tid = threadIdx.x;
    const int wid = tid >> 5;
    const int lane = tid & 31;
    const int m0 = blockIdx.y * 256;
    const int wM = wid >> 2;         // 0..3
    const int wN = wid & 3;          // 0..3

    const __half* b_p;
    int n0, hsel, which = -1;
    if (mode == 3) {
        which = blockIdx.x >> 4;
        int nb = blockIdx.x & 15;
        n0 = nb * 128; hsel = nb;
        b_p = (which == 0) ? g_wqT : (which == 1) ? g_wkT : g_wvT;
    } else {
        n0 = blockIdx.x * 128; hsel = blockIdx.x;
        b_p = Bs;
    }

    const char* srcA = (const char*)(As + (size_t)m0 * E_DIM);
    const char* srcB = (const char*)(b_p + (size_t)n0 * E_DIM);

    auto issue_chunk = [&](int c, int p) {
        uint32_t sb = smem_base + p * STAGE_B;
        const int kb = c * 128;
#pragma unroll
        for (int i = 0; i < 4; i++) {
            int idx = tid + i * 512;
            int row = idx >> 3, c16 = idx & 7;
            uint32_t d = row * ROW_B + c16 * 16;
            CP_ASYNC16(sb + d, srcA + (size_t)row * 4096 + kb + c16 * 16);
        }
#pragma unroll
        for (int i = 0; i < 2; i++) {
            int idx = tid + i * 512;
            int row = idx >> 3, c16 = idx & 7;
            uint32_t d = row * ROW_B + c16 * 16;
            CP_ASYNC16(sb + A_TILE_B + d, srcB + (size_t)row * 4096 + kb + c16 * 16);
        }
    };

    float acc[4][4][4];
#pragma unroll
    for (int mt = 0; mt < 4; mt++)
#pragma unroll
        for (int nt = 0; nt < 4; nt++)
#pragma unroll
            for (int e = 0; e < 4; e++) acc[mt][nt][e] = 0.0f;

    const int a_row = (lane & 15);
    const int a_kb = (lane >> 4) * 16;
    const int b_nrow = (lane & 7) | ((lane & 16) >> 1);
    const int b_kb = (lane & 8) ? 16 : 0;

    issue_chunk(0, 0);
    CP_COMMIT();

    for (int c = 0; c < 32; c++) {
        if (c + 1 < 32) {
            issue_chunk(c + 1, (c + 1) & 1);
            CP_COMMIT();
            CP_WAIT1();
        } else {
            CP_WAIT0();
        }
        __syncthreads();

        uint32_t sb = smem_base + (c & 1) * STAGE_B;
        uint32_t aA = sb + (wM * 64 + a_row) * ROW_B + a_kb;
        uint32_t bB = sb + A_TILE_B + (wN * 32 + b_nrow) * ROW_B + b_kb;

#pragma unroll
        for (int ks = 0; ks < 4; ks++) {
            uint32_t a[4][4], b[4][2];
#pragma unroll
            for (int mt = 0; mt < 4; mt++) {
                LDSM4(a[mt][0], a[mt][1], a[mt][2], a[mt][3],
                      aA + mt * (16 * ROW_B) + ks * 32);
            }
#pragma unroll
            for (int bt = 0; bt < 2; bt++) {
                LDSM4(b[bt * 2][0], b[bt * 2][1], b[bt * 2 + 1][0], b[bt * 2 + 1][1],
                      bB + bt * (16 * ROW_B) + ks * 32);
            }
#pragma unroll
            for (int mt = 0; mt < 4; mt++)
#pragma unroll
                for (int nt = 0; nt < 4; nt++)
                    MMA16816(acc[mt][nt], a[mt], b[nt]);
        }
        __syncthreads();
    }

    // epilogue through smem so RoPE pairs d/d+64 are thread-local
    float* csm = (float*)smem;     // [256][132]
    const int g = lane >> 2;
    const int tg = lane & 3;
#pragma unroll
    for (int mt = 0; mt < 4; mt++)
#pragma unroll
        for (int nt = 0; nt < 4; nt++) {
            int r = wM * 64 + mt * 16 + g;
            int col = wN * 32 + nt * 8 + tg * 2;
            csm[r * 132 + col]           = acc[mt][nt][0];
            csm[r * 132 + col + 1]       = acc[mt][nt][1];
            csm[(r + 8) * 132 + col]     = acc[mt][nt][2];
            csm[(r + 8) * 132 + col + 1] = acc[mt][nt][3];
        }
    __syncthreads();

#pragma unroll 4
    for (int it = 0; it < 32; it++) {
        int idx = tid + it * 512;
        int row = idx >> 6;
        int d = idx & 63;
        float lo = csm[row * 132 + d];
        float hi = csm[row * 132 + d + 64];
        int s = m0 + row;
        if (mode == 0) {
            float* orow = outf + (size_t)s * E_DIM + n0;
            orow[d] = lo;
            orow[d + 64] = hi;
        } else {
            if (which <= 1) {              // RoPE for Q and K
                float ang = rope[s * (D_HEAD / 2) + d];
                float sn, cs;
                __sincosf(ang, &sn, &cs);
                float nlo = lo * cs - hi * sn;
                float nhi = hi * cs + lo * sn;
                lo = nlo; hi = nhi;
            }
            size_t base = ((size_t)hsel * S_DIM + s) * D_HEAD;
            __half* dst = (which == 0) ? g_q16 : (which == 1) ? g_k16 : g_v16;
            dst[base + d]      = __float2half(lo);
            dst[base + d + 64] = __float2half(hi);
        }
    }
}

// ---------------------------------------------------------------------------
// Block-sparse attention, single-term fp16 mma.sync, CTA per (q-tile, head).
// R12: R10 schedule (single-buffer K/V, prefetch AFTER consumer loop) +
// diag softmax jmax skip (bit-identical) + LPT ordering (t reversed so the
// heaviest q-tiles launch first; makespan shrinks under HW work-stealing).
// smem: Q, K, V  (3 x 32KB, 256B swizzled rows)
// ---------------------------------------------------------------------------
#define NEG_BIG (-1e10f)
#define ATT_TILE 32768
#define ATT_SMEM (3 * ATT_TILE)   // 98304

__global__ __launch_bounds__(256, 1)
void attn_mma(const int* __restrict__ anchors, int kanch)
{
    extern __shared__ char smn[];
    __shared__ int s_tiles[16];
    __shared__ int s_cnt;
    const uint32_t base = smem_u32(smn);
    const uint32_t Qb = base;
    const uint32_t Kb = base + ATT_TILE;
    const uint32_t Vb = base + 2 * ATT_TILE;

    const int t = T_NUM - 1 - blockIdx.x;   // LPT: heavy tiles (large t) first
    const int h = blockIdx.y;
    const int tid = threadIdx.x;
    const int w = tid >> 5, lane = tid & 31;
    const int g = lane >> 2, tq = lane & 3;
    const float scale = 0.088388347648318447f;

    // build filtered tile list: anchors <= t (duplicates kept), then local t
    const int abase = (h * T_NUM + t) * kanch;
    if (tid == 0) {
        int n = 0;
        for (int i = 0; i < kanch; i++) {
            int a = anchors[abase + i];
            if (a <= t) s_tiles[n++] = a;
        }
        s_tiles[n++] = t;
        s_cnt = n;
    }
    __syncthreads();
    const int cnt = s_cnt;
    int tile = s_tiles[0];

    auto load_tile = [&](uint32_t dst, const __half* src, int tl) {
        const char* p = (const char*)(src + ((size_t)h * S_DIM + (size_t)tl * 128) * D_HEAD);
        for (int i = tid; i < 2048; i += 256) {
            int row = i >> 4, c16 = i & 15;
            uint32_t off = row * 256 + ((c16 ^ (row & 7)) << 4);
            CP_ASYNC16(dst + off, p + (size_t)row * 256 + c16 * 16);
        }
    };

    // group0: Q + K0 ; group1: V0
    load_tile(Qb, g_q16, t);
    load_tile(Kb, g_k16, tile);
    CP_COMMIT();
    load_tile(Vb, g_v16, tile);
    CP_COMMIT();

    float o[16][4];
#pragma unroll
    for (int j = 0; j < 16; j++)
#pragma unroll
        for (int e = 0; e < 4; e++) o[j][e] = 0.0f;
    float m0 = -1e30f, m1 = -1e30f, l0 = 0.0f, l1 = 0.0f;

    const int wrow = w * 16;
    const int arow = wrow + (lane & 15);
    const int asw = arow & 7;
    const int ahc = lane >> 4;
    const int bnr = (lane & 7) | ((lane & 16) >> 1);
    const int bhc = (lane & 8) >> 3;
    const int vrl = lane & 15;
    const int vhc = lane >> 4;

    for (int it = 0; it < cnt; it++) {
        const bool have_next = (it + 1 < cnt);
        const int nx = have_next ? s_tiles[it + 1] : 0;
        const bool isdiag = (tile == t);   // causal structure inside this tile

        CP_WAIT1();          // K_it (and Q on it==0) ready
        __syncthreads();

        // ---- S = Q K^T (single term); skip fully-masked K blocks on diag ----
        float s[16][4];
#pragma unroll
        for (int j = 0; j < 16; j++)
#pragma unroll
            for (int e = 0; e < 4; e++) s[j][e] = 0.0f;

#pragma unroll
        for (int ks = 0; ks < 8; ks++) {
            uint32_t q4[4];
            uint32_t aoff = arow * 256 + (((ks * 2 + ahc) ^ asw) << 4);
            LDSM4(q4[0], q4[1], q4[2], q4[3], Qb + aoff);
#pragma unroll
            for (int nb = 0; nb < 8; nb++) {
                if (isdiag && nb > w) continue;   // keys 16nb.. all future of row 16w+15
                int br = nb * 16 + bnr;
                uint32_t boff = br * 256 + (((ks * 2 + bhc) ^ (br & 7)) << 4);
                uint32_t k4[4];
                LDSM4(k4[0], k4[1], k4[2], k4[3], Kb + boff);
                uint32_t b0[2] = {k4[0], k4[1]}, b1[2] = {k4[2], k4[3]};
                MMA16816(s[2 * nb],     q4, b0);
                MMA16816(s[2 * nb + 1], q4, b1);
            }
        }
        __syncthreads();                 // all warps done reading K
        if (have_next) load_tile(Kb, g_k16, nx);
        CP_COMMIT();

        // ---- mask + online softmax (live fragments only; quad shuffles) ----
        const int jmax = isdiag ? (2 * w + 2) : 16;   // frags >= jmax fully masked
        const int qp0 = t * 128 + wrow + g;
        const int qp1 = qp0 + 8;
        const int kb = tile * 128 + 2 * tq;
        float mx0 = -1e30f, mx1 = -1e30f;
#pragma unroll
        for (int j = 0; j < 16; j++) {
            if (j >= jmax) continue;
            int kc = kb + 8 * j;
            s[j][0] = (kc     > qp0) ? NEG_BIG : s[j][0] * scale;
            s[j][1] = (kc + 1 > qp0) ? NEG_BIG : s[j][1] * scale;
            s[j][2] = (kc     > qp1) ? NEG_BIG : s[j][2] * scale;
            s[j][3] = (kc + 1 > qp1) ? NEG_BIG : s[j][3] * scale;
            mx0 = fmaxf(mx0, fmaxf(s[j][0], s[j][1]));
            mx1 = fmaxf(mx1, fmaxf(s[j][2], s[j][3]));
        }
        mx0 = fmaxf(mx0, __shfl_xor_sync(0xffffffffu, mx0, 1));
        mx0 = fmaxf(mx0, __shfl_xor_sync(0xffffffffu, mx0, 2));
        mx1 = fmaxf(mx1, __shfl_xor_sync(0xffffffffu, mx1, 1));
        mx1 = fmaxf(mx1, __shfl_xor_sync(0xffffffffu, mx1, 2));
        const float mn0 = fmaxf(m0, mx0), mn1 = fmaxf(m1, mx1);
        const float f0 = __expf(m0 - mn0), f1 = __expf(m1 - mn1);
        float ls0 = 0.0f, ls1 = 0.0f;
#pragma unroll
        for (int j = 0; j < 16; j++) {
            if (j >= jmax) continue;
            s[j][0] = __expf(s[j][0] - mn0);
            s[j][1] = __expf(s[j][1] - mn0);
            s[j][2] = __expf(s[j][2] - mn1);
            s[j][3] = __expf(s[j][3] - mn1);
            ls0 += s[j][0] + s[j][1];
            ls1 += s[j][2] + s[j][3];
        }
        ls0 += __shfl_xor_sync(0xffffffffu, ls0, 1);
        ls0 += __shfl_xor_sync(0xffffffffu, ls0, 2);
        ls1 += __shfl_xor_sync(0xffffffffu, ls1, 1);
        ls1 += __shfl_xor_sync(0xffffffffu, ls1, 2);
        l0 = l0 * f0 + ls0; l1 = l1 * f1 + ls1;
        m0 = mn0; m1 = mn1;
#pragma unroll
        for (int j = 0; j < 16; j++) {
            o[j][0] *= f0; o[j][1] *= f0;
            o[j][2] *= f1; o[j][3] *= f1;
        }

        CP_WAIT1();          // V_it ready
        __syncthreads();

        // ---- O += P V (single term); skip all-zero P chunks on diag ----
#pragma unroll
        for (int ks = 0; ks < 8; ks++) {
            if (isdiag && ks > w) continue;   // P columns 16ks.. all zero for this warp
            uint32_t ph[4];
            ph[0] = pack_h2(s[2 * ks][0], s[2 * ks][1]);
            ph[1] = pack_h2(s[2 * ks][2], s[2 * ks][3]);
            ph[2] = pack_h2(s[2 * ks + 1][0], s[2 * ks + 1][1]);
            ph[3] = pack_h2(s[2 * ks + 1][2], s[2 * ks + 1][3]);
            int vr = ks * 16 + vrl;
#pragma unroll
            for (int dd = 0; dd < 8; dd++) {
                uint32_t voff = vr * 256 + (((dd * 2 + vhc) ^ (vr & 7)) << 4);
                uint32_t v4[4];
                LDSM4T(v4[0], v4[1], v4[2], v4[3], Vb + voff);
                uint32_t b0[2] = {v4[0], v4[1]}, b1[2] = {v4[2], v4[3]};
                MMA16816(o[2 * dd],     ph, b0);
                MMA16816(o[2 * dd + 1], ph, b1);
            }
        }
        __syncthreads();                 // all warps done reading V
        if (have_next) load_tile(Vb, g_v16, nx);
        CP_COMMIT();

        tile = nx;
    }

    // ---- epilogue: normalize, fp16 att to [S, H*D] ----
    const float i0 = 1.0f / l0, i1 = 1.0f / l1;
    const int s0 = t * 128 + wrow + g, s1 = s0 + 8;
#pragma unroll
    for (int j = 0; j < 16; j++) {
        int col = h * D_HEAD + 8 * j + 2 * tq;
        *(uint32_t*)(g_att + (size_t)s0 * E_DIM + col) = pack_h2(o[j][0] * i0, o[j][1] * i0);
        *(uint32_t*)(g_att + (size_t)s1 * E_DIM + col) = pack_h2(o[j][2] * i1, o[j][3] * i1);
    }
}

// ---------------------------------------------------------------------------
extern "C" void kernel_launch(void* const* d_in, const int* in_sizes, int n_in,
                              void* d_out, int out_size)
{
    const float* x    = (const float*)d_in[0];
    const float* wq   = (const float*)d_in[1];
    const float* wk   = (const float*)d_in[2];
    const float* wv   = (const float*)d_in[3];
    const float* wo   = (const float*)d_in[4];
    const float* rope = (const float*)d_in[5];
    const int* anchors = (const int*)d_in[6];
    float* out = (float*)d_out;

    const int kanch = in_sizes[6] / (H_NUM * T_NUM);  // 8

    __half *x16, *woT, *att;
    cudaGetSymbolAddress((void**)&x16, g_x16);
    cudaGetSymbolAddress((void**)&woT, g_woT);
    cudaGetSymbolAddress((void**)&att, g_att);

    cudaFuncSetAttribute(gemm_mma, cudaFuncAttributeMaxDynamicSharedMemorySize, GEMM_SMEM);
    cudaFuncSetAttribute(attn_mma, cudaFuncAttributeMaxDynamicSharedMemorySize, ATT_SMEM);

    // 1. convert x -> fp16
    convert_kernel<<<(S_DIM * E_DIM / 4 + 255) / 256, 256>>>(x, x16, S_DIM * E_DIM);

    // 2. fused transpose of all weights (single fp16)
    dim3 tgrid(E_DIM / 32, E_DIM / 32, 4), tblk(32, 8);
    transpose4<<<tgrid, tblk>>>(wq, wk, wv, wo);

    // 3. fused QKV projection (RoPE inside), head-major fp16
    dim3 qkvgrid(48, S_DIM / 256);  // (48, 16)
    gemm_mma<<<qkvgrid, 512, GEMM_SMEM>>>(x16, nullptr, nullptr, rope, 3);

    // 4. block-sparse attention (tile-skip + causal skips + LPT ordering)
    dim3 agrid(T_NUM, H_NUM);
    attn_mma<<<agrid, 256, ATT_SMEM>>>(anchors, kanch);

    // 5. out projection -> d_out
    dim3 ogrid(E_DIM / 128, S_DIM / 256);  // (16, 16)
    gemm_mma<<<ogrid, 512, GEMM_SMEM>>>(att, woT, out, nullptr, 0);
}

// round 13
// speedup vs baseline: 1.0609x; 1.0527x over previous
#include <cuda_runtime.h>
#include <cuda_fp16.h>
#include <math.h>
#include <stdint.h>

#define S_DIM 4096
#define E_DIM 2048
#define H_NUM 16
#define D_HEAD 128
#define T_NUM 32

// ---------------------------------------------------------------------------
// Scratch (__device__ globals; allocation-free rule) — single fp16 pipeline
// ---------------------------------------------------------------------------
__device__ __half g_x16[S_DIM * E_DIM];
__device__ __half g_wqT[E_DIM * E_DIM];
__device__ __half g_wkT[E_DIM * E_DIM];
__device__ __half g_wvT[E_DIM * E_DIM];
__device__ __half g_woT[E_DIM * E_DIM];
__device__ __half g_q16[H_NUM * S_DIM * D_HEAD];
__device__ __half g_k16[H_NUM * S_DIM * D_HEAD];
__device__ __half g_v16[H_NUM * S_DIM * D_HEAD];
__device__ __half g_att[S_DIM * E_DIM];

// ---------------------------------------------------------------------------
// base-ISA PTX helpers (compute_103 virtual arch: no tcgen05/TMA)
// ---------------------------------------------------------------------------
__device__ __forceinline__ uint32_t smem_u32(const void* p) {
    uint32_t a;
    asm("{ .reg .u64 t; cvta.to.shared.u64 t, %1; cvt.u32.u64 %0, t; }" : "=r"(a) : "l"(p));
    return a;
}

#define CP_ASYNC16(dst, src) \
    asm volatile("cp.async.cg.shared.global [%0], [%1], 16;" :: "r"(dst), "l"(src))
#define CP_COMMIT() asm volatile("cp.async.commit_group;" ::: "memory")
#define CP_WAIT1() asm volatile("cp.async.wait_group 1;" ::: "memory")
#define CP_WAIT0() asm volatile("cp.async.wait_group 0;" ::: "memory")

#define LDSM4(r0, r1, r2, r3, addr) \
    asm volatile("ldmatrix.sync.aligned.m8n8.x4.shared.b16 {%0,%1,%2,%3}, [%4];" \
        : "=r"(r0), "=r"(r1), "=r"(r2), "=r"(r3) : "r"(addr))
#define LDSM4T(r0, r1, r2, r3, addr) \
    asm volatile("ldmatrix.sync.aligned.m8n8.x4.trans.shared.b16 {%0,%1,%2,%3}, [%4];" \
        : "=r"(r0), "=r"(r1), "=r"(r2), "=r"(r3) : "r"(addr))

#define MMA16816(d, a, b) \
    asm volatile("mma.sync.aligned.m16n8k16.row.col.f32.f16.f16.f32 " \
        "{%0,%1,%2,%3}, {%4,%5,%6,%7}, {%8,%9}, {%0,%1,%2,%3};" \
        : "+f"((d)[0]), "+f"((d)[1]), "+f"((d)[2]), "+f"((d)[3]) \
        : "r"((a)[0]), "r"((a)[1]), "r"((a)[2]), "r"((a)[3]), \
          "r"((b)[0]), "r"((b)[1]))

__device__ __forceinline__ uint32_t pack_h2(float a, float b) {
    __half2 v = __floats2half2_rn(a, b);
    return *(uint32_t*)&v;
}

// ---------------------------------------------------------------------------
// Fused prep: z=0..3 -> transpose weight matrix to [N,K] fp16;
//             z=4    -> convert x fp32 -> fp16
// One launch instead of two; memory-bound phases share the chip.
// ---------------------------------------------------------------------------
__global__ void prep_kernel(const float* __restrict__ x,
                            const float* __restrict__ wq, const float* __restrict__ wk,
                            const float* __restrict__ wv, const float* __restrict__ wo)
{
    __shared__ float tile[32][33];
    if (blockIdx.z == 4) {
        // convert x: 4096 blocks x 256 threads x 8 elems = 8,388,608
        int b = blockIdx.y * 64 + blockIdx.x;
        int tid = threadIdx.y * 32 + threadIdx.x;
        int i = b * 2048 + tid * 8;
        float4 v0 = *(const float4*)(x + i);
        float4 v1 = *(const float4*)(x + i + 4);
        *(__half2*)(g_x16 + i)     = __floats2half2_rn(v0.x, v0.y);
        *(__half2*)(g_x16 + i + 2) = __floats2half2_rn(v0.z, v0.w);
        *(__half2*)(g_x16 + i + 4) = __floats2half2_rn(v1.x, v1.y);
        *(__half2*)(g_x16 + i + 6) = __floats2half2_rn(v1.z, v1.w);
        return;
    }
    const float* w;
    __half* oT;
    switch (blockIdx.z) {
        case 0:  w = wq; oT = g_wqT; break;
        case 1:  w = wk; oT = g_wkT; break;
        case 2:  w = wv; oT = g_wvT; break;
        default: w = wo; oT = g_woT; break;
    }
    int n = blockIdx.x * 32 + threadIdx.x;
    int k0 = blockIdx.y * 32;
#pragma unroll
    for (int j = 0; j < 32; j += 8)
        tile[threadIdx.y + j][threadIdx.x] = w[(k0 + threadIdx.y + j) * E_DIM + n];
    __syncthreads();
#pragma unroll
    for (int j = 0; j < 32; j += 8) {
        int orow = blockIdx.x * 32 + threadIdx.y + j;
        int ocol = k0 + threadIdx.x;
        oT[orow * E_DIM + ocol] = __float2half(tile[threadIdx.x][threadIdx.y + j]);
    }
}

// ---------------------------------------------------------------------------
// HMMA fp16 GEMM — single-term. CTA 256x128, 512 threads (16 warps 4Mx4N),
// K-chunk 64, cp.async double buffer. (At the mma.sync issue-rate wall.)
// mode 0: fp32 row-major out[M,2048] (A = g_att, B = woT)
// mode 3: fused QKV — blockIdx.x = which*16 + nb; RoPE for Q,K; fp16 outs
// ---------------------------------------------------------------------------
#define ROW_B 144
#define A_TILE_B (256 * ROW_B)       // 36864
#define B_TILE_B (128 * ROW_B)       // 18432
#define STAGE_B (A_TILE_B + B_TILE_B)  // 55296
#define EPI_B (256 * 132 * 4)        // 135168 fp32 epilogue tile
#define GEMM_SMEM (EPI_B > 2 * STAGE_B ? EPI_B : 2 * STAGE_B)   // 135168

__global__ __launch_bounds__(512, 1)
void gemm_mma(const __half* __restrict__ As, const __half* __restrict__ Bs,
              float* __restrict__ outf, const float* __restrict__ rope, int mode)
{
    extern __shared__ char smem[];
    const uint32_t smem_base = smem_u32(smem);
    const int tid = threadIdx.x;
    const int wid = tid >> 5;
    const int lane = tid & 31;
    const int m0 = blockIdx.y * 256;
    const int wM = wid >> 2;         // 0..3
    const int wN = wid & 3;          // 0..3

    const __half* b_p;
    int n0, hsel, which = -1;
    if (mode == 3) {
        which = blockIdx.x >> 4;
        int nb = blockIdx.x & 15;
        n0 = nb * 128; hsel = nb;
        b_p = (which == 0) ? g_wqT : (which == 1) ? g_wkT : g_wvT;
    } else {
        n0 = blockIdx.x * 128; hsel = blockIdx.x;
        b_p = Bs;
    }

    const char* srcA = (const char*)(As + (size_t)m0 * E_DIM);
    const char* srcB = (const char*)(b_p + (size_t)n0 * E_DIM);

    auto issue_chunk = [&](int c, int p) {
        uint32_t sb = smem_base + p * STAGE_B;
        const int kb = c * 128;
#pragma unroll
        for (int i = 0; i < 4; i++) {
            int idx = tid + i * 512;
            int row = idx >> 3, c16 = idx & 7;
            uint32_t d = row * ROW_B + c16 * 16;
            CP_ASYNC16(sb + d, srcA + (size_t)row * 4096 + kb + c16 * 16);
        }
#pragma unroll
        for (int i = 0; i < 2; i++) {
            int idx = tid + i * 512;
            int row = idx >> 3, c16 = idx & 7;
            uint32_t d = row * ROW_B + c16 * 16;
            CP_ASYNC16(sb + A_TILE_B + d, srcB + (size_t)row * 4096 + kb + c16 * 16);
        }
    };

    float acc[4][4][4];
#pragma unroll
    for (int mt = 0; mt < 4; mt++)
#pragma unroll
        for (int nt = 0; nt < 4; nt++)
#pragma unroll
            for (int e = 0; e < 4; e++) acc[mt][nt][e] = 0.0f;

    const int a_row = (lane & 15);
    const int a_kb = (lane >> 4) * 16;
    const int b_nrow = (lane & 7) | ((lane & 16) >> 1);
    const int b_kb = (lane & 8) ? 16 : 0;

    issue_chunk(0, 0);
    CP_COMMIT();

    for (int c = 0; c < 32; c++) {
        if (c + 1 < 32) {
            issue_chunk(c + 1, (c + 1) & 1);
            CP_COMMIT();
            CP_WAIT1();
        } else {
            CP_WAIT0();
        }
        __syncthreads();

        uint32_t sb = smem_base + (c & 1) * STAGE_B;
        uint32_t aA = sb + (wM * 64 + a_row) * ROW_B + a_kb;
        uint32_t bB = sb + A_TILE_B + (wN * 32 + b_nrow) * ROW_B + b_kb;

#pragma unroll
        for (int ks = 0; ks < 4; ks++) {
            uint32_t a[4][4], b[4][2];
#pragma unroll
            for (int mt = 0; mt < 4; mt++) {
                LDSM4(a[mt][0], a[mt][1], a[mt][2], a[mt][3],
                      aA + mt * (16 * ROW_B) + ks * 32);
            }
#pragma unroll
            for (int bt = 0; bt < 2; bt++) {
                LDSM4(b[bt * 2][0], b[bt * 2][1], b[bt * 2 + 1][0], b[bt * 2 + 1][1],
                      bB + bt * (16 * ROW_B) + ks * 32);
            }
#pragma unroll
            for (int mt = 0; mt < 4; mt++)
#pragma unroll
                for (int nt = 0; nt < 4; nt++)
                    MMA16816(acc[mt][nt], a[mt], b[nt]);
        }
        __syncthreads();
    }

    // epilogue through smem so RoPE pairs d/d+64 are thread-local
    float* csm = (float*)smem;     // [256][132]
    const int g = lane >> 2;
    const int tg = lane & 3;
#pragma unroll
    for (int mt = 0; mt < 4; mt++)
#pragma unroll
        for (int nt = 0; nt < 4; nt++) {
            int r = wM * 64 + mt * 16 + g;
            int col = wN * 32 + nt * 8 + tg * 2;
            csm[r * 132 + col]           = acc[mt][nt][0];
            csm[r * 132 + col + 1]       = acc[mt][nt][1];
            csm[(r + 8) * 132 + col]     = acc[mt][nt][2];
            csm[(r + 8) * 132 + col + 1] = acc[mt][nt][3];
        }
    __syncthreads();

#pragma unroll 4
    for (int it = 0; it < 32; it++) {
        int idx = tid + it * 512;
        int row = idx >> 6;
        int d = idx & 63;
        float lo = csm[row * 132 + d];
        float hi = csm[row * 132 + d + 64];
        int s = m0 + row;
        if (mode == 0) {
            float* orow = outf + (size_t)s * E_DIM + n0;
            orow[d] = lo;
            orow[d + 64] = hi;
        } else {
            if (which <= 1) {              // RoPE for Q and K
                float ang = rope[s * (D_HEAD / 2) + d];
                float sn, cs;
                __sincosf(ang, &sn, &cs);
                float nlo = lo * cs - hi * sn;
                float nhi = hi * cs + lo * sn;
                lo = nlo; hi = nhi;
            }
            size_t base = ((size_t)hsel * S_DIM + s) * D_HEAD;
            __half* dst = (which == 0) ? g_q16 : (which == 1) ? g_k16 : g_v16;
            dst[base + d]      = __float2half(lo);
            dst[base + d + 64] = __float2half(hi);
        }
    }
}

// ---------------------------------------------------------------------------
// Block-sparse attention — EXACT R10 code (best measured: 123us).
// Single-term fp16 mma.sync, CTA per (q-tile, head); fully-masked anchor
// tiles skipped (exact); intra-diagonal MMA-level causal skip (exact).
// smem: Q, K, V  (3 x 32KB, 256B swizzled rows)
// ---------------------------------------------------------------------------
#define NEG_BIG (-1e10f)
#define ATT_TILE 32768
#define ATT_SMEM (3 * ATT_TILE)   // 98304

__global__ __launch_bounds__(256, 1)
void attn_mma(const int* __restrict__ anchors, int kanch)
{
    extern __shared__ char smn[];
    __shared__ int s_tiles[16];
    __shared__ int s_cnt;
    const uint32_t base = smem_u32(smn);
    const uint32_t Qb = base;
    const uint32_t Kb = base + ATT_TILE;
    const uint32_t Vb = base + 2 * ATT_TILE;

    const int t = blockIdx.x, h = blockIdx.y;
    const int tid = threadIdx.x;
    const int w = tid >> 5, lane = tid & 31;
    const int g = lane >> 2, tq = lane & 3;
    const float scale = 0.088388347648318447f;

    // build filtered tile list: anchors <= t (duplicates kept), then local t
    const int abase = (h * T_NUM + t) * kanch;
    if (tid == 0) {
        int n = 0;
        for (int i = 0; i < kanch; i++) {
            int a = anchors[abase + i];
            if (a <= t) s_tiles[n++] = a;
        }
        s_tiles[n++] = t;
        s_cnt = n;
    }
    __syncthreads();
    const int cnt = s_cnt;
    int tile = s_tiles[0];

    auto load_tile = [&](uint32_t dst, const __half* src, int tl) {
        const char* p = (const char*)(src + ((size_t)h * S_DIM + (size_t)tl * 128) * D_HEAD);
        for (int i = tid; i < 2048; i += 256) {
            int row = i >> 4, c16 = i & 15;
            uint32_t off = row * 256 + ((c16 ^ (row & 7)) << 4);
            CP_ASYNC16(dst + off, p + (size_t)row * 256 + c16 * 16);
        }
    };

    // group0: Q + K0 ; group1: V0
    load_tile(Qb, g_q16, t);
    load_tile(Kb, g_k16, tile);
    CP_COMMIT();
    load_tile(Vb, g_v16, tile);
    CP_COMMIT();

    float o[16][4];
#pragma unroll
    for (int j = 0; j < 16; j++)
#pragma unroll
        for (int e = 0; e < 4; e++) o[j][e] = 0.0f;
    float m0 = -1e30f, m1 = -1e30f, l0 = 0.0f, l1 = 0.0f;

    const int wrow = w * 16;
    const int arow = wrow + (lane & 15);
    const int asw = arow & 7;
    const int ahc = lane >> 4;
    const int bnr = (lane & 7) | ((lane & 16) >> 1);
    const int bhc = (lane & 8) >> 3;
    const int vrl = lane & 15;
    const int vhc = lane >> 4;

    for (int it = 0; it < cnt; it++) {
        const bool have_next = (it + 1 < cnt);
        const int nx = have_next ? s_tiles[it + 1] : 0;
        const bool isdiag = (tile == t);   // causal structure inside this tile

        CP_WAIT1();          // K_it (and Q on it==0) ready
        __syncthreads();

        // ---- S = Q K^T (single term); skip fully-masked K blocks on diag ----
        float s[16][4];
#pragma unroll
        for (int j = 0; j < 16; j++)
#pragma unroll
            for (int e = 0; e < 4; e++) s[j][e] = 0.0f;

#pragma unroll
        for (int ks = 0; ks < 8; ks++) {
            uint32_t q4[4];
            uint32_t aoff = arow * 256 + (((ks * 2 + ahc) ^ asw) << 4);
            LDSM4(q4[0], q4[1], q4[2], q4[3], Qb + aoff);
#pragma unroll
            for (int nb = 0; nb < 8; nb++) {
                if (isdiag && nb > w) continue;   // keys 16nb.. all future of row 16w+15
                int br = nb * 16 + bnr;
                uint32_t boff = br * 256 + (((ks * 2 + bhc) ^ (br & 7)) << 4);
                uint32_t k4[4];
                LDSM4(k4[0], k4[1], k4[2], k4[3], Kb + boff);
                uint32_t b0[2] = {k4[0], k4[1]}, b1[2] = {k4[2], k4[3]};
                MMA16816(s[2 * nb],     q4, b0);
                MMA16816(s[2 * nb + 1], q4, b1);
            }
        }
        __syncthreads();                 // all warps done reading K
        if (have_next) load_tile(Kb, g_k16, nx);
        CP_COMMIT();

        // ---- mask + online softmax (quad shuffles only) ----
        const int qp0 = t * 128 + wrow + g;
        const int qp1 = qp0 + 8;
        const int kb = tile * 128 + 2 * tq;
        float mx0 = -1e30f, mx1 = -1e30f;
#pragma unroll
        for (int j = 0; j < 16; j++) {
            int kc = kb + 8 * j;
            s[j][0] = (kc     > qp0) ? NEG_BIG : s[j][0] * scale;
            s[j][1] = (kc + 1 > qp0) ? NEG_BIG : s[j][1] * scale;
            s[j][2] = (kc     > qp1) ? NEG_BIG : s[j][2] * scale;
            s[j][3] = (kc + 1 > qp1) ? NEG_BIG : s[j][3] * scale;
            mx0 = fmaxf(mx0, fmaxf(s[j][0], s[j][1]));
            mx1 = fmaxf(mx1, fmaxf(s[j][2], s[j][3]));
        }
        mx0 = fmaxf(mx0, __shfl_xor_sync(0xffffffffu, mx0, 1));
        mx0 = fmaxf(mx0, __shfl_xor_sync(0xffffffffu, mx0, 2));
        mx1 = fmaxf(mx1, __shfl_xor_sync(0xffffffffu, mx1, 1));
        mx1 = fmaxf(mx1, __shfl_xor_sync(0xffffffffu, mx1, 2));
        const float mn0 = fmaxf(m0, mx0), mn1 = fmaxf(m1, mx1);
        const float f0 = __expf(m0 - mn0), f1 = __expf(m1 - mn1);
        float ls0 = 0.0f, ls1 = 0.0f;
#pragma unroll
        for (int j = 0; j < 16; j++) {
            s[j][0] = __expf(s[j][0] - mn0);
            s[j][1] = __expf(s[j][1] - mn0);
            s[j][2] = __expf(s[j][2] - mn1);
            s[j][3] = __expf(s[j][3] - mn1);
            ls0 += s[j][0] + s[j][1];
            ls1 += s[j][2] + s[j][3];
        }
        ls0 += __shfl_xor_sync(0xffffffffu, ls0, 1);
        ls0 += __shfl_xor_sync(0xffffffffu, ls0, 2);
        ls1 += __shfl_xor_sync(0xffffffffu, ls1, 1);
        ls1 += __shfl_xor_sync(0xffffffffu, ls1, 2);
        l0 = l0 * f0 + ls0; l1 = l1 * f1 + ls1;
        m0 = mn0; m1 = mn1;
#pragma unroll
        for (int j = 0; j < 16; j++) {
            o[j][0] *= f0; o[j][1] *= f0;
            o[j][2] *= f1; o[j][3] *= f1;
        }

        CP_WAIT1();          // V_it ready
        __syncthreads();

        // ---- O += P V (single term); skip all-zero P chunks on diag ----
#pragma unroll
        for (int ks = 0; ks < 8; ks++) {
            if (isdiag && ks > w) continue;   // P columns 16ks.. all zero for this warp
            uint32_t ph[4];
            ph[0] = pack_h2(s[2 * ks][0], s[2 * ks][1]);
            ph[1] = pack_h2(s[2 * ks][2], s[2 * ks][3]);
            ph[2] = pack_h2(s[2 * ks + 1][0], s[2 * ks + 1][1]);
            ph[3] = pack_h2(s[2 * ks + 1][2], s[2 * ks + 1][3]);
            int vr = ks * 16 + vrl;
#pragma unroll
            for (int dd = 0; dd < 8; dd++) {
                uint32_t voff = vr * 256 + (((dd * 2 + vhc) ^ (vr & 7)) << 4);
                uint32_t v4[4];
                LDSM4T(v4[0], v4[1], v4[2], v4[3], Vb + voff);
                uint32_t b0[2] = {v4[0], v4[1]}, b1[2] = {v4[2], v4[3]};
                MMA16816(o[2 * dd],     ph, b0);
                MMA16816(o[2 * dd + 1], ph, b1);
            }
        }
        __syncthreads();                 // all warps done reading V
        if (have_next) load_tile(Vb, g_v16, nx);
        CP_COMMIT();

        tile = nx;
    }

    // ---- epilogue: normalize, fp16 att to [S, H*D] ----
    const float i0 = 1.0f / l0, i1 = 1.0f / l1;
    const int s0 = t * 128 + wrow + g, s1 = s0 + 8;
#pragma unroll
    for (int j = 0; j < 16; j++) {
        int col = h * D_HEAD + 8 * j + 2 * tq;
        *(uint32_t*)(g_att + (size_t)s0 * E_DIM + col) = pack_h2(o[j][0] * i0, o[j][1] * i0);
        *(uint32_t*)(g_att + (size_t)s1 * E_DIM + col) = pack_h2(o[j][2] * i1, o[j][3] * i1);
    }
}

// ---------------------------------------------------------------------------
extern "C" void kernel_launch(void* const* d_in, const int* in_sizes, int n_in,
                              void* d_out, int out_size)
{
    const float* x    = (const float*)d_in[0];
    const float* wq   = (const float*)d_in[1];
    const float* wk   = (const float*)d_in[2];
    const float* wv   = (const float*)d_in[3];
    const float* wo   = (const float*)d_in[4];
    const float* rope = (const float*)d_in[5];
    const int* anchors = (const int*)d_in[6];
    float* out = (float*)d_out;

    const int kanch = in_sizes[6] / (H_NUM * T_NUM);  // 8

    __half *x16, *woT, *att;
    cudaGetSymbolAddress((void**)&x16, g_x16);
    cudaGetSymbolAddress((void**)&woT, g_woT);
    cudaGetSymbolAddress((void**)&att, g_att);

    cudaFuncSetAttribute(gemm_mma, cudaFuncAttributeMaxDynamicSharedMemorySize, GEMM_SMEM);
    cudaFuncSetAttribute(attn_mma, cudaFuncAttributeMaxDynamicSharedMemorySize, ATT_SMEM);

    // 1. fused prep: weight transposes (z=0..3) + x convert (z=4)
    dim3 pgrid(E_DIM / 32, E_DIM / 32, 5), pblk(32, 8);
    prep_kernel<<<pgrid, pblk>>>(x, wq, wk, wv, wo);

    // 2. fused QKV projection (RoPE inside), head-major fp16
    dim3 qkvgrid(48, S_DIM / 256);  // (48, 16)
    gemm_mma<<<qkvgrid, 512, GEMM_SMEM>>>(x16, nullptr, nullptr, rope, 3);

    // 3. block-sparse attention (R10-exact: tile-skip + MMA-level causal skip)
    dim3 agrid(T_NUM, H_NUM);
    attn_mma<<<agrid, 256, ATT_SMEM>>>(anchors, kanch);

    // 4. out projection -> d_out
    dim3 ogrid(E_DIM / 128, S_DIM / 256);  // (16, 16)
    gemm_mma<<<ogrid, 512, GEMM_SMEM>>>(att, woT, out, nullptr, 0);
}

// round 14
// speedup vs baseline: 1.1293x; 1.0645x over previous
#include <cuda_runtime.h>
#include <cuda_fp16.h>
#include <math.h>
#include <stdint.h>

#define S_DIM 4096
#define E_DIM 2048
#define H_NUM 16
#define D_HEAD 128
#define T_NUM 32

// ---------------------------------------------------------------------------
// Scratch (__device__ globals; allocation-free rule) — single fp16 pipeline
// ---------------------------------------------------------------------------
__device__ __half g_x16[S_DIM * E_DIM];
__device__ __half g_wqT[E_DIM * E_DIM];
__device__ __half g_wkT[E_DIM * E_DIM];
__device__ __half g_wvT[E_DIM * E_DIM];
__device__ __half g_woT[E_DIM * E_DIM];
__device__ __half g_q16[H_NUM * S_DIM * D_HEAD];
__device__ __half g_k16[H_NUM * S_DIM * D_HEAD];
__device__ __half g_v16[H_NUM * S_DIM * D_HEAD];
__device__ __half g_att[S_DIM * E_DIM];

// ---------------------------------------------------------------------------
// base-ISA PTX helpers (compute_103 virtual arch: no tcgen05/TMA)
// ---------------------------------------------------------------------------
__device__ __forceinline__ uint32_t smem_u32(const void* p) {
    uint32_t a;
    asm("{ .reg .u64 t; cvta.to.shared.u64 t, %1; cvt.u32.u64 %0, t; }" : "=r"(a) : "l"(p));
    return a;
}

#define CP_ASYNC16(dst, src) \
    asm volatile("cp.async.cg.shared.global [%0], [%1], 16;" :: "r"(dst), "l"(src))
#define CP_COMMIT() asm volatile("cp.async.commit_group;" ::: "memory")
#define CP_WAIT1() asm volatile("cp.async.wait_group 1;" ::: "memory")
#define CP_WAIT0() asm volatile("cp.async.wait_group 0;" ::: "memory")

#define LDSM4(r0, r1, r2, r3, addr) \
    asm volatile("ldmatrix.sync.aligned.m8n8.x4.shared.b16 {%0,%1,%2,%3}, [%4];" \
        : "=r"(r0), "=r"(r1), "=r"(r2), "=r"(r3) : "r"(addr))
#define LDSM4T(r0, r1, r2, r3, addr) \
    asm volatile("ldmatrix.sync.aligned.m8n8.x4.trans.shared.b16 {%0,%1,%2,%3}, [%4];" \
        : "=r"(r0), "=r"(r1), "=r"(r2), "=r"(r3) : "r"(addr))

#define MMA16816(d, a, b) \
    asm volatile("mma.sync.aligned.m16n8k16.row.col.f32.f16.f16.f32 " \
        "{%0,%1,%2,%3}, {%4,%5,%6,%7}, {%8,%9}, {%0,%1,%2,%3};" \
        : "+f"((d)[0]), "+f"((d)[1]), "+f"((d)[2]), "+f"((d)[3]) \
        : "r"((a)[0]), "r"((a)[1]), "r"((a)[2]), "r"((a)[3]), \
          "r"((b)[0]), "r"((b)[1]))

__device__ __forceinline__ uint32_t pack_h2(float a, float b) {
    __half2 v = __floats2half2_rn(a, b);
    return *(uint32_t*)&v;
}

// ---------------------------------------------------------------------------
// Fused prep: z=0..3 -> transpose weight matrix to [N,K] fp16;
//             z=4    -> convert x fp32 -> fp16
// ---------------------------------------------------------------------------
__global__ void prep_kernel(const float* __restrict__ x,
                            const float* __restrict__ wq, const float* __restrict__ wk,
                            const float* __restrict__ wv, const float* __restrict__ wo)
{
    __shared__ float tile[32][33];
    if (blockIdx.z == 4) {
        int b = blockIdx.y * 64 + blockIdx.x;
        int tid = threadIdx.y * 32 + threadIdx.x;
        int i = b * 2048 + tid * 8;
        float4 v0 = *(const float4*)(x + i);
        float4 v1 = *(const float4*)(x + i + 4);
        *(__half2*)(g_x16 + i)     = __floats2half2_rn(v0.x, v0.y);
        *(__half2*)(g_x16 + i + 2) = __floats2half2_rn(v0.z, v0.w);
        *(__half2*)(g_x16 + i + 4) = __floats2half2_rn(v1.x, v1.y);
        *(__half2*)(g_x16 + i + 6) = __floats2half2_rn(v1.z, v1.w);
        return;
    }
    const float* w;
    __half* oT;
    switch (blockIdx.z) {
        case 0:  w = wq; oT = g_wqT; break;
        case 1:  w = wk; oT = g_wkT; break;
        case 2:  w = wv; oT = g_wvT; break;
        default: w = wo; oT = g_woT; break;
    }
    int n = blockIdx.x * 32 + threadIdx.x;
    int k0 = blockIdx.y * 32;
#pragma unroll
    for (int j = 0; j < 32; j += 8)
        tile[threadIdx.y + j][threadIdx.x] = w[(k0 + threadIdx.y + j) * E_DIM + n];
    __syncthreads();
#pragma unroll
    for (int j = 0; j < 32; j += 8) {
        int orow = blockIdx.x * 32 + threadIdx.y + j;
        int ocol = k0 + threadIdx.x;
        oT[orow * E_DIM + ocol] = __float2half(tile[threadIdx.x][threadIdx.y + j]);
    }
}

// ---------------------------------------------------------------------------
// HMMA fp16 GEMM — single-term. CTA 256x128, 512 threads (16 warps 4Mx4N),
// K-chunk 64, **3-stage cp.async pipeline with ONE barrier per chunk**:
// prefetch of chunk c+2 is issued after the barrier, into the stage last
// read at iteration c-1 (WAR-safe since all warps passed the barrier).
// mode 0: fp32 row-major out[M,2048] (A = g_att, B = woT)
// mode 3: fused QKV — blockIdx.x = which*16 + nb; RoPE for Q,K; fp16 outs
// ---------------------------------------------------------------------------
#define ROW_B 144
#define A_TILE_B (256 * ROW_B)       // 36864
#define B_TILE_B (128 * ROW_B)       // 18432
#define STAGE_B (A_TILE_B + B_TILE_B)  // 55296
#define EPI_B (256 * 132 * 4)        // 135168 fp32 epilogue tile
#define PIPE_B (3 * STAGE_B)         // 165888
#define GEMM_SMEM (EPI_B > PIPE_B ? EPI_B : PIPE_B)   // 165888

__global__ __launch_bounds__(512, 1)
void gemm_mma(const __half* __restrict__ As, const __half* __restrict__ Bs,
              float* __restrict__ outf, const float* __restrict__ rope, int mode)
{
    extern __shared__ char smem[];
    const uint32_t smem_base = smem_u32(smem);
    const int tid = threadIdx.x;
    const int wid = tid >> 5;
    const int lane = tid & 31;
    const int m0 = blockIdx.y * 256;
    const int wM = wid >> 2;         // 0..3
    const int wN = wid & 3;          // 0..3

    const __half* b_p;
    int n0, hsel, which = -1;
    if (mode == 3) {
        which = blockIdx.x >> 4;
        int nb = blockIdx.x & 15;
        n0 = nb * 128; hsel = nb;
        b_p = (which == 0) ? g_wqT : (which == 1) ? g_wkT : g_wvT;
    } else {
        n0 = blockIdx.x * 128; hsel = blockIdx.x;
        b_p = Bs;
    }

    const char* srcA = (const char*)(As + (size_t)m0 * E_DIM);
    const char* srcB = (const char*)(b_p + (size_t)n0 * E_DIM);

    auto issue_chunk = [&](int c, int st) {
        uint32_t sb = smem_base + st * STAGE_B;
        const int kb = c * 128;
#pragma unroll
        for (int i = 0; i < 4; i++) {
            int idx = tid + i * 512;
            int row = idx >> 3, c16 = idx & 7;
            uint32_t d = row * ROW_B + c16 * 16;
            CP_ASYNC16(sb + d, srcA + (size_t)row * 4096 + kb + c16 * 16);
        }
#pragma unroll
        for (int i = 0; i < 2; i++) {
            int idx = tid + i * 512;
            int row = idx >> 3, c16 = idx & 7;
            uint32_t d = row * ROW_B + c16 * 16;
            CP_ASYNC16(sb + A_TILE_B + d, srcB + (size_t)row * 4096 + kb + c16 * 16);
        }
    };

    float acc[4][4][4];
#pragma unroll
    for (int mt = 0; mt < 4; mt++)
#pragma unroll
        for (int nt = 0; nt < 4; nt++)
#pragma unroll
            for (int e = 0; e < 4; e++) acc[mt][nt][e] = 0.0f;

    const int a_row = (lane & 15);
    const int a_kb = (lane >> 4) * 16;
    const int b_nrow = (lane & 7) | ((lane & 16) >> 1);
    const int b_kb = (lane & 8) ? 16 : 0;

    // prologue: 2 chunks in flight
    issue_chunk(0, 0); CP_COMMIT();
    issue_chunk(1, 1); CP_COMMIT();

    int st = 0;   // stage of chunk c
    for (int c = 0; c < 32; c++) {
        if (c == 31) { CP_WAIT0(); } else { CP_WAIT1(); }   // chunk c landed
        __syncthreads();   // all warps done reading stage (c+2)%3 (at iter c-1)

        if (c + 2 < 32) {
            int st2 = st + 2; if (st2 >= 3) st2 -= 3;
            issue_chunk(c + 2, st2);
            CP_COMMIT();
        }

        uint32_t sb = smem_base + st * STAGE_B;
        uint32_t aA = sb + (wM * 64 + a_row) * ROW_B + a_kb;
        uint32_t bB = sb + A_TILE_B + (wN * 32 + b_nrow) * ROW_B + b_kb;

#pragma unroll
        for (int ks = 0; ks < 4; ks++) {
            uint32_t a[4][4], b[4][2];
#pragma unroll
            for (int mt = 0; mt < 4; mt++) {
                LDSM4(a[mt][0], a[mt][1], a[mt][2], a[mt][3],
                      aA + mt * (16 * ROW_B) + ks * 32);
            }
#pragma unroll
            for (int bt = 0; bt < 2; bt++) {
                LDSM4(b[bt * 2][0], b[bt * 2][1], b[bt * 2 + 1][0], b[bt * 2 + 1][1],
                      bB + bt * (16 * ROW_B) + ks * 32);
            }
#pragma unroll
            for (int mt = 0; mt < 4; mt++)
#pragma unroll
                for (int nt = 0; nt < 4; nt++)
                    MMA16816(acc[mt][nt], a[mt], b[nt]);
        }

        if (++st >= 3) st -= 3;
    }
    __syncthreads();   // protect epilogue smem reuse against last compute reads

    // epilogue through smem so RoPE pairs d/d+64 are thread-local
    float* csm = (float*)smem;     // [256][132]
    const int g = lane >> 2;
    const int tg = lane & 3;
#pragma unroll
    for (int mt = 0; mt < 4; mt++)
#pragma unroll
        for (int nt = 0; nt < 4; nt++) {
            int r = wM * 64 + mt * 16 + g;
            int col = wN * 32 + nt * 8 + tg * 2;
            csm[r * 132 + col]           = acc[mt][nt][0];
            csm[r * 132 + col + 1]       = acc[mt][nt][1];
            csm[(r + 8) * 132 + col]     = acc[mt][nt][2];
            csm[(r + 8) * 132 + col + 1] = acc[mt][nt][3];
        }
    __syncthreads();

#pragma unroll 4
    for (int it = 0; it < 32; it++) {
        int idx = tid + it * 512;
        int row = idx >> 6;
        int d = idx & 63;
        float lo = csm[row * 132 + d];
        float hi = csm[row * 132 + d + 64];
        int s = m0 + row;
        if (mode == 0) {
            float* orow = outf + (size_t)s * E_DIM + n0;
            orow[d] = lo;
            orow[d + 64] = hi;
        } else {
            if (which <= 1) {              // RoPE for Q and K
                float ang = rope[s * (D_HEAD / 2) + d];
                float sn, cs;
                __sincosf(ang, &sn, &cs);
                float nlo = lo * cs - hi * sn;
                float nhi = hi * cs + lo * sn;
                lo = nlo; hi = nhi;
            }
            size_t base = ((size_t)hsel * S_DIM + s) * D_HEAD;
            __half* dst = (which == 0) ? g_q16 : (which == 1) ? g_k16 : g_v16;
            dst[base + d]      = __float2half(lo);
            dst[base + d + 64] = __float2half(hi);
        }
    }
}

// ---------------------------------------------------------------------------
// Block-sparse attention — EXACT R10 code (best measured: 123us).
// Single-term fp16 mma.sync, CTA per (q-tile, head); fully-masked anchor
// tiles skipped (exact); intra-diagonal MMA-level causal skip (exact).
// smem: Q, K, V  (3 x 32KB, 256B swizzled rows)
// ---------------------------------------------------------------------------
#define NEG_BIG (-1e10f)
#define ATT_TILE 32768
#define ATT_SMEM (3 * ATT_TILE)   // 98304

__global__ __launch_bounds__(256, 1)
void attn_mma(const int* __restrict__ anchors, int kanch)
{
    extern __shared__ char smn[];
    __shared__ int s_tiles[16];
    __shared__ int s_cnt;
    const uint32_t base = smem_u32(smn);
    const uint32_t Qb = base;
    const uint32_t Kb = base + ATT_TILE;
    const uint32_t Vb = base + 2 * ATT_TILE;

    const int t = blockIdx.x, h = blockIdx.y;
    const int tid = threadIdx.x;
    const int w = tid >> 5, lane = tid & 31;
    const int g = lane >> 2, tq = lane & 3;
    const float scale = 0.088388347648318447f;

    const int abase = (h * T_NUM + t) * kanch;
    if (tid == 0) {
        int n = 0;
        for (int i = 0; i < kanch; i++) {
            int a = anchors[abase + i];
            if (a <= t) s_tiles[n++] = a;
        }
        s_tiles[n++] = t;
        s_cnt = n;
    }
    __syncthreads();
    const int cnt = s_cnt;
    int tile = s_tiles[0];

    auto load_tile = [&](uint32_t dst, const __half* src, int tl) {
        const char* p = (const char*)(src + ((size_t)h * S_DIM + (size_t)tl * 128) * D_HEAD);
        for (int i = tid; i < 2048; i += 256) {
            int row = i >> 4, c16 = i & 15;
            uint32_t off = row * 256 + ((c16 ^ (row & 7)) << 4);
            CP_ASYNC16(dst + off, p + (size_t)row * 256 + c16 * 16);
        }
    };

    load_tile(Qb, g_q16, t);
    load_tile(Kb, g_k16, tile);
    CP_COMMIT();
    load_tile(Vb, g_v16, tile);
    CP_COMMIT();

    float o[16][4];
#pragma unroll
    for (int j = 0; j < 16; j++)
#pragma unroll
        for (int e = 0; e < 4; e++) o[j][e] = 0.0f;
    float m0 = -1e30f, m1 = -1e30f, l0 = 0.0f, l1 = 0.0f;

    const int wrow = w * 16;
    const int arow = wrow + (lane & 15);
    const int asw = arow & 7;
    const int ahc = lane >> 4;
    const int bnr = (lane & 7) | ((lane & 16) >> 1);
    const int bhc = (lane & 8) >> 3;
    const int vrl = lane & 15;
    const int vhc = lane >> 4;

    for (int it = 0; it < cnt; it++) {
        const bool have_next = (it + 1 < cnt);
        const int nx = have_next ? s_tiles[it + 1] : 0;
        const bool isdiag = (tile == t);

        CP_WAIT1();
        __syncthreads();

        float s[16][4];
#pragma unroll
        for (int j = 0; j < 16; j++)
#pragma unroll
            for (int e = 0; e < 4; e++) s[j][e] = 0.0f;

#pragma unroll
        for (int ks = 0; ks < 8; ks++) {
            uint32_t q4[4];
            uint32_t aoff = arow * 256 + (((ks * 2 + ahc) ^ asw) << 4);
            LDSM4(q4[0], q4[1], q4[2], q4[3], Qb + aoff);
#pragma unroll
            for (int nb = 0; nb < 8; nb++) {
                if (isdiag && nb > w) continue;
                int br = nb * 16 + bnr;
                uint32_t boff = br * 256 + (((ks * 2 + bhc) ^ (br & 7)) << 4);
                uint32_t k4[4];
                LDSM4(k4[0], k4[1], k4[2], k4[3], Kb + boff);
                uint32_t b0[2] = {k4[0], k4[1]}, b1[2] = {k4[2], k4[3]};
                MMA16816(s[2 * nb],     q4, b0);
                MMA16816(s[2 * nb + 1], q4, b1);
            }
        }
        __syncthreads();
        if (have_next) load_tile(Kb, g_k16, nx);
        CP_COMMIT();

        const int qp0 = t * 128 + wrow + g;
        const int qp1 = qp0 + 8;
        const int kb = tile * 128 + 2 * tq;
        float mx0 = -1e30f, mx1 = -1e30f;
#pragma unroll
        for (int j = 0; j < 16; j++) {
            int kc = kb + 8 * j;
            s[j][0] = (kc     > qp0) ? NEG_BIG : s[j][0] * scale;
            s[j][1] = (kc + 1 > qp0) ? NEG_BIG : s[j][1] * scale;
            s[j][2] = (kc     > qp1) ? NEG_BIG : s[j][2] * scale;
            s[j][3] = (kc + 1 > qp1) ? NEG_BIG : s[j][3] * scale;
            mx0 = fmaxf(mx0, fmaxf(s[j][0], s[j][1]));
            mx1 = fmaxf(mx1, fmaxf(s[j][2], s[j][3]));
        }
        mx0 = fmaxf(mx0, __shfl_xor_sync(0xffffffffu, mx0, 1));
        mx0 = fmaxf(mx0, __shfl_xor_sync(0xffffffffu, mx0, 2));
        mx1 = fmaxf(mx1, __shfl_xor_sync(0xffffffffu, mx1, 1));
        mx1 = fmaxf(mx1, __shfl_xor_sync(0xffffffffu, mx1, 2));
        const float mn0 = fmaxf(m0, mx0), mn1 = fmaxf(m1, mx1);
        const float f0 = __expf(m0 - mn0), f1 = __expf(m1 - mn1);
        float ls0 = 0.0f, ls1 = 0.0f;
#pragma unroll
        for (int j = 0; j < 16; j++) {
            s[j][0] = __expf(s[j][0] - mn0);
            s[j][1] = __expf(s[j][1] - mn0);
            s[j][2] = __expf(s[j][2] - mn1);
            s[j][3] = __expf(s[j][3] - mn1);
            ls0 += s[j][0] + s[j][1];
            ls1 += s[j][2] + s[j][3];
        }
        ls0 += __shfl_xor_sync(0xffffffffu, ls0, 1);
        ls0 += __shfl_xor_sync(0xffffffffu, ls0, 2);
        ls1 += __shfl_xor_sync(0xffffffffu, ls1, 1);
        ls1 += __shfl_xor_sync(0xffffffffu, ls1, 2);
        l0 = l0 * f0 + ls0; l1 = l1 * f1 + ls1;
        m0 = mn0; m1 = mn1;
#pragma unroll
        for (int j = 0; j < 16; j++) {
            o[j][0] *= f0; o[j][1] *= f0;
            o[j][2] *= f1; o[j][3] *= f1;
        }

        CP_WAIT1();
        __syncthreads();

#pragma unroll
        for (int ks = 0; ks < 8; ks++) {
            if (isdiag && ks > w) continue;
            uint32_t ph[4];
            ph[0] = pack_h2(s[2 * ks][0], s[2 * ks][1]);
            ph[1] = pack_h2(s[2 * ks][2], s[2 * ks][3]);
            ph[2] = pack_h2(s[2 * ks + 1][0], s[2 * ks + 1][1]);
            ph[3] = pack_h2(s[2 * ks + 1][2], s[2 * ks + 1][3]);
            int vr = ks * 16 + vrl;
#pragma unroll
            for (int dd = 0; dd < 8; dd++) {
                uint32_t voff = vr * 256 + (((dd * 2 + vhc) ^ (vr & 7)) << 4);
                uint32_t v4[4];
                LDSM4T(v4[0], v4[1], v4[2], v4[3], Vb + voff);
                uint32_t b0[2] = {v4[0], v4[1]}, b1[2] = {v4[2], v4[3]};
                MMA16816(o[2 * dd],     ph, b0);
                MMA16816(o[2 * dd + 1], ph, b1);
            }
        }
        __syncthreads();
        if (have_next) load_tile(Vb, g_v16, nx);
        CP_COMMIT();

        tile = nx;
    }

    const float i0 = 1.0f / l0, i1 = 1.0f / l1;
    const int s0 = t * 128 + wrow + g, s1 = s0 + 8;
#pragma unroll
    for (int j = 0; j < 16; j++) {
        int col = h * D_HEAD + 8 * j + 2 * tq;
        *(uint32_t*)(g_att + (size_t)s0 * E_DIM + col) = pack_h2(o[j][0] * i0, o[j][1] * i0);
        *(uint32_t*)(g_att + (size_t)s1 * E_DIM + col) = pack_h2(o[j][2] * i1, o[j][3] * i1);
    }
}

// ---------------------------------------------------------------------------
extern "C" void kernel_launch(void* const* d_in, const int* in_sizes, int n_in,
                              void* d_out, int out_size)
{
    const float* x    = (const float*)d_in[0];
    const float* wq   = (const float*)d_in[1];
    const float* wk   = (const float*)d_in[2];
    const float* wv   = (const float*)d_in[3];
    const float* wo   = (const float*)d_in[4];
    const float* rope = (const float*)d_in[5];
    const int* anchors = (const int*)d_in[6];
    float* out = (float*)d_out;

    const int kanch = in_sizes[6] / (H_NUM * T_NUM);  // 8

    __half *x16, *woT, *att;
    cudaGetSymbolAddress((void**)&x16, g_x16);
    cudaGetSymbolAddress((void**)&woT, g_woT);
    cudaGetSymbolAddress((void**)&att, g_att);

    cudaFuncSetAttribute(gemm_mma, cudaFuncAttributeMaxDynamicSharedMemorySize, GEMM_SMEM);
    cudaFuncSetAttribute(attn_mma, cudaFuncAttributeMaxDynamicSharedMemorySize, ATT_SMEM);

    // 1. fused prep: weight transposes (z=0..3) + x convert (z=4)
    dim3 pgrid(E_DIM / 32, E_DIM / 32, 5), pblk(32, 8);
    prep_kernel<<<pgrid, pblk>>>(x, wq, wk, wv, wo);

    // 2. fused QKV projection (RoPE inside), head-major fp16
    dim3 qkvgrid(48, S_DIM / 256);  // (48, 16)
    gemm_mma<<<qkvgrid, 512, GEMM_SMEM>>>(x16, nullptr, nullptr, rope, 3);

    // 3. block-sparse attention (R10-exact)
    dim3 agrid(T_NUM, H_NUM);
    attn_mma<<<agrid, 256, ATT_SMEM>>>(anchors, kanch);

    // 4. out projection -> d_out
    dim3 ogrid(E_DIM / 128, S_DIM / 256);  // (16, 16)
    gemm_mma<<<ogrid, 512, GEMM_SMEM>>>(att, woT, out, nullptr, 0);
}

// round 15
// speedup vs baseline: 1.2304x; 1.0896x over previous
#include <cuda_runtime.h>
#include <cuda_fp16.h>
#include <math.h>
#include <stdint.h>

#define S_DIM 4096
#define E_DIM 2048
#define H_NUM 16
#define D_HEAD 128
#define T_NUM 32

// ---------------------------------------------------------------------------
// Scratch (__device__ globals; allocation-free rule) — single fp16 pipeline
// ---------------------------------------------------------------------------
__device__ __half g_x16[S_DIM * E_DIM];
__device__ __half g_wqT[E_DIM * E_DIM];
__device__ __half g_wkT[E_DIM * E_DIM];
__device__ __half g_wvT[E_DIM * E_DIM];
__device__ __half g_woT[E_DIM * E_DIM];
__device__ __half g_q16[H_NUM * S_DIM * D_HEAD];
__device__ __half g_k16[H_NUM * S_DIM * D_HEAD];
__device__ __half g_v16[H_NUM * S_DIM * D_HEAD];
__device__ __half g_att[S_DIM * E_DIM];

// ---------------------------------------------------------------------------
// base-ISA PTX helpers (compute_103 virtual arch: no tcgen05/TMA)
// ---------------------------------------------------------------------------
__device__ __forceinline__ uint32_t smem_u32(const void* p) {
    uint32_t a;
    asm("{ .reg .u64 t; cvta.to.shared.u64 t, %1; cvt.u32.u64 %0, t; }" : "=r"(a) : "l"(p));
    return a;
}

#define CP_ASYNC16(dst, src) \
    asm volatile("cp.async.cg.shared.global [%0], [%1], 16;" :: "r"(dst), "l"(src))
#define CP_COMMIT() asm volatile("cp.async.commit_group;" ::: "memory")
#define CP_WAIT1() asm volatile("cp.async.wait_group 1;" ::: "memory")
#define CP_WAIT0() asm volatile("cp.async.wait_group 0;" ::: "memory")

#define LDSM4(r0, r1, r2, r3, addr) \
    asm volatile("ldmatrix.sync.aligned.m8n8.x4.shared.b16 {%0,%1,%2,%3}, [%4];" \
        : "=r"(r0), "=r"(r1), "=r"(r2), "=r"(r3) : "r"(addr))
#define LDSM4T(r0, r1, r2, r3, addr) \
    asm volatile("ldmatrix.sync.aligned.m8n8.x4.trans.shared.b16 {%0,%1,%2,%3}, [%4];" \
        : "=r"(r0), "=r"(r1), "=r"(r2), "=r"(r3) : "r"(addr))

#define MMA16816(d, a, b) \
    asm volatile("mma.sync.aligned.m16n8k16.row.col.f32.f16.f16.f32 " \
        "{%0,%1,%2,%3}, {%4,%5,%6,%7}, {%8,%9}, {%0,%1,%2,%3};" \
        : "+f"((d)[0]), "+f"((d)[1]), "+f"((d)[2]), "+f"((d)[3]) \
        : "r"((a)[0]), "r"((a)[1]), "r"((a)[2]), "r"((a)[3]), \
          "r"((b)[0]), "r"((b)[1]))

__device__ __forceinline__ uint32_t pack_h2(float a, float b) {
    __half2 v = __floats2half2_rn(a, b);
    return *(uint32_t*)&v;
}

// ---------------------------------------------------------------------------
// Fused prep: z=0..3 -> transpose weight matrix to [N,K] fp16;
//             z=4    -> convert x fp32 -> fp16
// ---------------------------------------------------------------------------
__global__ void prep_kernel(const float* __restrict__ x,
                            const float* __restrict__ wq, const float* __restrict__ wk,
                            const float* __restrict__ wv, const float* __restrict__ wo)
{
    __shared__ float tile[32][33];
    if (blockIdx.z == 4) {
        int b = blockIdx.y * 64 + blockIdx.x;
        int tid = threadIdx.y * 32 + threadIdx.x;
        int i = b * 2048 + tid * 8;
        float4 v0 = *(const float4*)(x + i);
        float4 v1 = *(const float4*)(x + i + 4);
        *(__half2*)(g_x16 + i)     = __floats2half2_rn(v0.x, v0.y);
        *(__half2*)(g_x16 + i + 2) = __floats2half2_rn(v0.z, v0.w);
        *(__half2*)(g_x16 + i + 4) = __floats2half2_rn(v1.x, v1.y);
        *(__half2*)(g_x16 + i + 6) = __floats2half2_rn(v1.z, v1.w);
        return;
    }
    const float* w;
    __half* oT;
    switch (blockIdx.z) {
        case 0:  w = wq; oT = g_wqT; break;
        case 1:  w = wk; oT = g_wkT; break;
        case 2:  w = wv; oT = g_wvT; break;
        default: w = wo; oT = g_woT; break;
    }
    int n = blockIdx.x * 32 + threadIdx.x;
    int k0 = blockIdx.y * 32;
#pragma unroll
    for (int j = 0; j < 32; j += 8)
        tile[threadIdx.y + j][threadIdx.x] = w[(k0 + threadIdx.y + j) * E_DIM + n];
    __syncthreads();
#pragma unroll
    for (int j = 0; j < 32; j += 8) {
        int orow = blockIdx.x * 32 + threadIdx.y + j;
        int ocol = k0 + threadIdx.x;
        oT[orow * E_DIM + ocol] = __float2half(tile[threadIdx.x][threadIdx.y + j]);
    }
}

// ---------------------------------------------------------------------------
// HMMA fp16 GEMM — CTA 128x128, 128 threads (4 warps, 2x2 of 64x64 warp
// tiles: 33% less LDSM crossbar traffic, 32-MMA ILP per warp-ks), 2 CTAs/SM,
// K-chunk 64, 3-stage cp.async pipeline with ONE barrier per chunk.
// mode 0: fp32 row-major out[M,2048] (A = g_att, B = woT)
// mode 3: fused QKV — blockIdx.x = which*16 + nb; RoPE for Q,K; fp16 outs
// ---------------------------------------------------------------------------
#define ROW_B 144
#define A_TILE_B (128 * ROW_B)       // 18432
#define B_TILE_B (128 * ROW_B)       // 18432
#define STAGE_B (A_TILE_B + B_TILE_B)  // 36864
#define EPI_B (128 * 132 * 4)        // 67584 fp32 epilogue tile
#define PIPE_B (3 * STAGE_B)         // 110592
#define GEMM_SMEM (EPI_B > PIPE_B ? EPI_B : PIPE_B)   // 110592

__global__ __launch_bounds__(128, 2)
void gemm_mma(const __half* __restrict__ As, const __half* __restrict__ Bs,
              float* __restrict__ outf, const float* __restrict__ rope, int mode)
{
    extern __shared__ char smem[];
    const uint32_t smem_base = smem_u32(smem);
    const int tid = threadIdx.x;
    const int wid = tid >> 5;
    const int lane = tid & 31;
    const int m0 = blockIdx.y * 128;
    const int wM = wid >> 1;         // 0..1
    const int wN = wid & 1;          // 0..1

    const __half* b_p;
    int n0, hsel, which = -1;
    if (mode == 3) {
        which = blockIdx.x >> 4;
        int nb = blockIdx.x & 15;
        n0 = nb * 128; hsel = nb;
        b_p = (which == 0) ? g_wqT : (which == 1) ? g_wkT : g_wvT;
    } else {
        n0 = blockIdx.x * 128; hsel = blockIdx.x;
        b_p = Bs;
    }

    const char* srcA = (const char*)(As + (size_t)m0 * E_DIM);
    const char* srcB = (const char*)(b_p + (size_t)n0 * E_DIM);

    auto issue_chunk = [&](int c, int st) {
        uint32_t sb = smem_base + st * STAGE_B;
        const int kb = c * 128;
#pragma unroll
        for (int i = 0; i < 8; i++) {
            int idx = tid + i * 128;
            int row = idx >> 3, c16 = idx & 7;
            uint32_t d = row * ROW_B + c16 * 16;
            CP_ASYNC16(sb + d,            srcA + (size_t)row * 4096 + kb + c16 * 16);
            CP_ASYNC16(sb + A_TILE_B + d, srcB + (size_t)row * 4096 + kb + c16 * 16);
        }
    };

    float acc[4][8][4];
#pragma unroll
    for (int mt = 0; mt < 4; mt++)
#pragma unroll
        for (int nt = 0; nt < 8; nt++)
#pragma unroll
            for (int e = 0; e < 4; e++) acc[mt][nt][e] = 0.0f;

    const int a_row = (lane & 15);
    const int a_kb = (lane >> 4) * 16;
    const int b_nrow = (lane & 7) | ((lane & 16) >> 1);
    const int b_kb = (lane & 8) ? 16 : 0;

    // prologue: 2 chunks in flight
    issue_chunk(0, 0); CP_COMMIT();
    issue_chunk(1, 1); CP_COMMIT();

    int st = 0;
    for (int c = 0; c < 32; c++) {
        if (c == 31) { CP_WAIT0(); } else { CP_WAIT1(); }
        __syncthreads();   // all warps done reading stage (c+2)%3 (at iter c-1)

        if (c + 2 < 32) {
            int st2 = st + 2; if (st2 >= 3) st2 -= 3;
            issue_chunk(c + 2, st2);
            CP_COMMIT();
        }

        uint32_t sb = smem_base + st * STAGE_B;
        uint32_t aA = sb + (wM * 64 + a_row) * ROW_B + a_kb;
        uint32_t bB = sb + A_TILE_B + (wN * 64 + b_nrow) * ROW_B + b_kb;

#pragma unroll
        for (int ks = 0; ks < 4; ks++) {
            uint32_t a[4][4], b[8][2];
#pragma unroll
            for (int mt = 0; mt < 4; mt++) {
                LDSM4(a[mt][0], a[mt][1], a[mt][2], a[mt][3],
                      aA + mt * (16 * ROW_B) + ks * 32);
            }
#pragma unroll
            for (int bt = 0; bt < 4; bt++) {
                LDSM4(b[bt * 2][0], b[bt * 2][1], b[bt * 2 + 1][0], b[bt * 2 + 1][1],
                      bB + bt * (16 * ROW_B) + ks * 32);
            }
#pragma unroll
            for (int mt = 0; mt < 4; mt++)
#pragma unroll
                for (int nt = 0; nt < 8; nt++)
                    MMA16816(acc[mt][nt], a[mt], b[nt]);
        }

        if (++st >= 3) st -= 3;
    }
    __syncthreads();   // protect epilogue smem reuse

    // epilogue through smem so RoPE pairs d/d+64 are thread-local
    float* csm = (float*)smem;     // [128][132]
    const int g = lane >> 2;
    const int tg = lane & 3;
#pragma unroll
    for (int mt = 0; mt < 4; mt++)
#pragma unroll
        for (int nt = 0; nt < 8; nt++) {
            int r = wM * 64 + mt * 16 + g;
            int col = wN * 64 + nt * 8 + tg * 2;
            csm[r * 132 + col]           = acc[mt][nt][0];
            csm[r * 132 + col + 1]       = acc[mt][nt][1];
            csm[(r + 8) * 132 + col]     = acc[mt][nt][2];
            csm[(r + 8) * 132 + col + 1] = acc[mt][nt][3];
        }
    __syncthreads();

#pragma unroll 4
    for (int it = 0; it < 64; it++) {
        int idx = tid + it * 128;          // 0..8191
        int row = idx >> 6;                // 0..127
        int d = idx & 63;
        float lo = csm[row * 132 + d];
        float hi = csm[row * 132 + d + 64];
        int s = m0 + row;
        if (mode == 0) {
            float* orow = outf + (size_t)s * E_DIM + n0;
            orow[d] = lo;
            orow[d + 64] = hi;
        } else {
            if (which <= 1) {              // RoPE for Q and K
                float ang = rope[s * (D_HEAD / 2) + d];
                float sn, cs;
                __sincosf(ang, &sn, &cs);
                float nlo = lo * cs - hi * sn;
                float nhi = hi * cs + lo * sn;
                lo = nlo; hi = nhi;
            }
            size_t base = ((size_t)hsel * S_DIM + s) * D_HEAD;
            __half* dst = (which == 0) ? g_q16 : (which == 1) ? g_k16 : g_v16;
            dst[base + d]      = __float2half(lo);
            dst[base + d + 64] = __float2half(hi);
        }
    }
}

// ---------------------------------------------------------------------------
// Block-sparse attention — EXACT R10 code (best measured: 123us).
// ---------------------------------------------------------------------------
#define NEG_BIG (-1e10f)
#define ATT_TILE 32768
#define ATT_SMEM (3 * ATT_TILE)   // 98304

__global__ __launch_bounds__(256, 1)
void attn_mma(const int* __restrict__ anchors, int kanch)
{
    extern __shared__ char smn[];
    __shared__ int s_tiles[16];
    __shared__ int s_cnt;
    const uint32_t base = smem_u32(smn);
    const uint32_t Qb = base;
    const uint32_t Kb = base + ATT_TILE;
    const uint32_t Vb = base + 2 * ATT_TILE;

    const int t = blockIdx.x, h = blockIdx.y;
    const int tid = threadIdx.x;
    const int w = tid >> 5, lane = tid & 31;
    const int g = lane >> 2, tq = lane & 3;
    const float scale = 0.088388347648318447f;

    const int abase = (h * T_NUM + t) * kanch;
    if (tid == 0) {
        int n = 0;
        for (int i = 0; i < kanch; i++) {
            int a = anchors[abase + i];
            if (a <= t) s_tiles[n++] = a;
        }
        s_tiles[n++] = t;
        s_cnt = n;
    }
    __syncthreads();
    const int cnt = s_cnt;
    int tile = s_tiles[0];

    auto load_tile = [&](uint32_t dst, const __half* src, int tl) {
        const char* p = (const char*)(src + ((size_t)h * S_DIM + (size_t)tl * 128) * D_HEAD);
        for (int i = tid; i < 2048; i += 256) {
            int row = i >> 4, c16 = i & 15;
            uint32_t off = row * 256 + ((c16 ^ (row & 7)) << 4);
            CP_ASYNC16(dst + off, p + (size_t)row * 256 + c16 * 16);
        }
    };

    load_tile(Qb, g_q16, t);
    load_tile(Kb, g_k16, tile);
    CP_COMMIT();
    load_tile(Vb, g_v16, tile);
    CP_COMMIT();

    float o[16][4];
#pragma unroll
    for (int j = 0; j < 16; j++)
#pragma unroll
        for (int e = 0; e < 4; e++) o[j][e] = 0.0f;
    float m0 = -1e30f, m1 = -1e30f, l0 = 0.0f, l1 = 0.0f;

    const int wrow = w * 16;
    const int arow = wrow + (lane & 15);
    const int asw = arow & 7;
    const int ahc = lane >> 4;
    const int bnr = (lane & 7) | ((lane & 16) >> 1);
    const int bhc = (lane & 8) >> 3;
    const int vrl = lane & 15;
    const int vhc = lane >> 4;

    for (int it = 0; it < cnt; it++) {
        const bool have_next = (it + 1 < cnt);
        const int nx = have_next ? s_tiles[it + 1] : 0;
        const bool isdiag = (tile == t);

        CP_WAIT1();
        __syncthreads();

        float s[16][4];
#pragma unroll
        for (int j = 0; j < 16; j++)
#pragma unroll
            for (int e = 0; e < 4; e++) s[j][e] = 0.0f;

#pragma unroll
        for (int ks = 0; ks < 8; ks++) {
            uint32_t q4[4];
            uint32_t aoff = arow * 256 + (((ks * 2 + ahc) ^ asw) << 4);
            LDSM4(q4[0], q4[1], q4[2], q4[3], Qb + aoff);
#pragma unroll
            for (int nb = 0; nb < 8; nb++) {
                if (isdiag && nb > w) continue;
                int br = nb * 16 + bnr;
                uint32_t boff = br * 256 + (((ks * 2 + bhc) ^ (br & 7)) << 4);
                uint32_t k4[4];
                LDSM4(k4[0], k4[1], k4[2], k4[3], Kb + boff);
                uint32_t b0[2] = {k4[0], k4[1]}, b1[2] = {k4[2], k4[3]};
                MMA16816(s[2 * nb],     q4, b0);
                MMA16816(s[2 * nb + 1], q4, b1);
            }
        }
        __syncthreads();
        if (have_next) load_tile(Kb, g_k16, nx);
        CP_COMMIT();

        const int qp0 = t * 128 + wrow + g;
        const int qp1 = qp0 + 8;
        const int kb = tile * 128 + 2 * tq;
        float mx0 = -1e30f, mx1 = -1e30f;
#pragma unroll
        for (int j = 0; j < 16; j++) {
            int kc = kb + 8 * j;
            s[j][0] = (kc     > qp0) ? NEG_BIG : s[j][0] * scale;
            s[j][1] = (kc + 1 > qp0) ? NEG_BIG : s[j][1] * scale;
            s[j][2] = (kc     > qp1) ? NEG_BIG : s[j][2] * scale;
            s[j][3] = (kc + 1 > qp1) ? NEG_BIG : s[j][3] * scale;
            mx0 = fmaxf(mx0, fmaxf(s[j][0], s[j][1]));
            mx1 = fmaxf(mx1, fmaxf(s[j][2], s[j][3]));
        }
        mx0 = fmaxf(mx0, __shfl_xor_sync(0xffffffffu, mx0, 1));
        mx0 = fmaxf(mx0, __shfl_xor_sync(0xffffffffu, mx0, 2));
        mx1 = fmaxf(mx1, __shfl_xor_sync(0xffffffffu, mx1, 1));
        mx1 = fmaxf(mx1, __shfl_xor_sync(0xffffffffu, mx1, 2));
        const float mn0 = fmaxf(m0, mx0), mn1 = fmaxf(m1, mx1);
        const float f0 = __expf(m0 - mn0), f1 = __expf(m1 - mn1);
        float ls0 = 0.0f, ls1 = 0.0f;
#pragma unroll
        for (int j = 0; j < 16; j++) {
            s[j][0] = __expf(s[j][0] - mn0);
            s[j][1] = __expf(s[j][1] - mn0);
            s[j][2] = __expf(s[j][2] - mn1);
            s[j][3] = __expf(s[j][3] - mn1);
            ls0 += s[j][0] + s[j][1];
            ls1 += s[j][2] + s[j][3];
        }
        ls0 += __shfl_xor_sync(0xffffffffu, ls0, 1);
        ls0 += __shfl_xor_sync(0xffffffffu, ls0, 2);
        ls1 += __shfl_xor_sync(0xffffffffu, ls1, 1);
        ls1 += __shfl_xor_sync(0xffffffffu, ls1, 2);
        l0 = l0 * f0 + ls0; l1 = l1 * f1 + ls1;
        m0 = mn0; m1 = mn1;
#pragma unroll
        for (int j = 0; j < 16; j++) {
            o[j][0] *= f0; o[j][1] *= f0;
            o[j][2] *= f1; o[j][3] *= f1;
        }

        CP_WAIT1();
        __syncthreads();

#pragma unroll
        for (int ks = 0; ks < 8; ks++) {
            if (isdiag && ks > w) continue;
            uint32_t ph[4];
            ph[0] = pack_h2(s[2 * ks][0], s[2 * ks][1]);
            ph[1] = pack_h2(s[2 * ks][2], s[2 * ks][3]);
            ph[2] = pack_h2(s[2 * ks + 1][0], s[2 * ks + 1][1]);
            ph[3] = pack_h2(s[2 * ks + 1][2], s[2 * ks + 1][3]);
            int vr = ks * 16 + vrl;
#pragma unroll
            for (int dd = 0; dd < 8; dd++) {
                uint32_t voff = vr * 256 + (((dd * 2 + vhc) ^ (vr & 7)) << 4);
                uint32_t v4[4];
                LDSM4T(v4[0], v4[1], v4[2], v4[3], Vb + voff);
                uint32_t b0[2] = {v4[0], v4[1]}, b1[2] = {v4[2], v4[3]};
                MMA16816(o[2 * dd],     ph, b0);
                MMA16816(o[2 * dd + 1], ph, b1);
            }
        }
        __syncthreads();
        if (have_next) load_tile(Vb, g_v16, nx);
        CP_COMMIT();

        tile = nx;
    }

    const float i0 = 1.0f / l0, i1 = 1.0f / l1;
    const int s0 = t * 128 + wrow + g, s1 = s0 + 8;
#pragma unroll
    for (int j = 0; j < 16; j++) {
        int col = h * D_HEAD + 8 * j + 2 * tq;
        *(uint32_t*)(g_att + (size_t)s0 * E_DIM + col) = pack_h2(o[j][0] * i0, o[j][1] * i0);
        *(uint32_t*)(g_att + (size_t)s1 * E_DIM + col) = pack_h2(o[j][2] * i1, o[j][3] * i1);
    }
}

// ---------------------------------------------------------------------------
extern "C" void kernel_launch(void* const* d_in, const int* in_sizes, int n_in,
                              void* d_out, int out_size)
{
    const float* x    = (const float*)d_in[0];
    const float* wq   = (const float*)d_in[1];
    const float* wk   = (const float*)d_in[2];
    const float* wv   = (const float*)d_in[3];
    const float* wo   = (const float*)d_in[4];
    const float* rope = (const float*)d_in[5];
    const int* anchors = (const int*)d_in[6];
    float* out = (float*)d_out;

    const int kanch = in_sizes[6] / (H_NUM * T_NUM);  // 8

    __half *x16, *woT, *att;
    cudaGetSymbolAddress((void**)&x16, g_x16);
    cudaGetSymbolAddress((void**)&woT, g_woT);
    cudaGetSymbolAddress((void**)&att, g_att);

    cudaFuncSetAttribute(gemm_mma, cudaFuncAttributeMaxDynamicSharedMemorySize, GEMM_SMEM);
    cudaFuncSetAttribute(attn_mma, cudaFuncAttributeMaxDynamicSharedMemorySize, ATT_SMEM);

    // 1. fused prep: weight transposes (z=0..3) + x convert (z=4)
    dim3 pgrid(E_DIM / 32, E_DIM / 32, 5), pblk(32, 8);
    prep_kernel<<<pgrid, pblk>>>(x, wq, wk, wv, wo);

    // 2. fused QKV projection (RoPE inside), head-major fp16
    dim3 qkvgrid(48, S_DIM / 128);  // (48, 32)
    gemm_mma<<<qkvgrid, 128, GEMM_SMEM>>>(x16, nullptr, nullptr, rope, 3);

    // 3. block-sparse attention (R10-exact)
    dim3 agrid(T_NUM, H_NUM);
    attn_mma<<<agrid, 256, ATT_SMEM>>>(anchors, kanch);

    // 4. out projection -> d_out
    dim3 ogrid(E_DIM / 128, S_DIM / 128);  // (16, 32)
    gemm_mma<<<ogrid, 128, GEMM_SMEM>>>(att, woT, out, nullptr, 0);
}